// round 2
// baseline (speedup 1.0000x reference)
#include <cuda_runtime.h>
#include <math.h>

#define BATCH 2
#define SEQ 4096
#define DM 1024
#define SD 16
#define M_ROWS (BATCH*SEQ)   // 8192

// ---------------- scratch (device globals; no allocations allowed) ----------
__device__ float g_delta[(size_t)M_ROWS * DM];   // softplus(x @ W_delta)
__device__ float g_Bsel [(size_t)M_ROWS * SD];
__device__ float g_Csel [(size_t)M_ROWS * SD];
__device__ float g_ssm  [(size_t)M_ROWS * DM];   // scan out, then LN in-place
__device__ float g_hfinal[BATCH * DM];
__device__ float g_hproj [BATCH * DM];
__device__ float g_raw  [M_ROWS];

// ---------------- classic 128x128x8 fp32 SGEMM, templated epilogue ----------
// EPI: 0 = multiply by *scale_ptr (or 1.0), 1 = softplus
template<int EPI>
__global__ void __launch_bounds__(256) sgemm_epi(
    const float* __restrict__ A, const float* __restrict__ B, float* __restrict__ C,
    int M, int N, int K, const float* __restrict__ scale_ptr)
{
    const int BK = 8;
    __shared__ float As[BK][128];
    __shared__ float Bs[BK][128];
    int tid  = threadIdx.x;
    int brow = blockIdx.y * 128, bcol = blockIdx.x * 128;
    int arow = tid >> 1,  acol = (tid & 1) * 4;        // A tile: 128x8 via float4
    int brw  = tid >> 5,  bcl  = (tid & 31) * 4;       // B tile: 8x128 via float4
    int trow = (tid >> 4) * 8, tcol = (tid & 15) * 8;  // 16x16 threads, 8x8 micro

    float acc[8][8];
#pragma unroll
    for (int i = 0; i < 8; i++)
#pragma unroll
        for (int j = 0; j < 8; j++) acc[i][j] = 0.f;

    const float* Aptr = A + (size_t)(brow + arow) * K + acol;
    const float* Bptr = B + (size_t)brw * N + bcol + bcl;

    for (int k0 = 0; k0 < K; k0 += BK) {
        float4 av = *(const float4*)(Aptr + k0);
        float4 bv = *(const float4*)(Bptr + (size_t)k0 * N);
        As[acol+0][arow] = av.x; As[acol+1][arow] = av.y;
        As[acol+2][arow] = av.z; As[acol+3][arow] = av.w;
        *(float4*)&Bs[brw][bcl] = bv;
        __syncthreads();
#pragma unroll
        for (int k = 0; k < BK; k++) {
            float ar[8], br[8];
            *(float4*)(ar)   = *(const float4*)&As[k][trow];
            *(float4*)(ar+4) = *(const float4*)&As[k][trow+4];
            *(float4*)(br)   = *(const float4*)&Bs[k][tcol];
            *(float4*)(br+4) = *(const float4*)&Bs[k][tcol+4];
#pragma unroll
            for (int i = 0; i < 8; i++)
#pragma unroll
                for (int j = 0; j < 8; j++)
                    acc[i][j] = fmaf(ar[i], br[j], acc[i][j]);
        }
        __syncthreads();
    }

    float scl = 1.0f;
    if (EPI == 0 && scale_ptr) scl = *scale_ptr;
#pragma unroll
    for (int i = 0; i < 8; i++) {
        float* crow = C + (size_t)(brow + trow + i) * N + bcol + tcol;
#pragma unroll
        for (int j = 0; j < 8; j++) {
            float v = acc[i][j];
            if (EPI == 1) {
                // stable softplus: max(v,0) + log1p(exp(-|v|))
                v = fmaxf(v, 0.f) + log1pf(__expf(-fabsf(v)));
            } else {
                v *= scl;
            }
            crow[j] = v;
        }
    }
}

// ---------------- B_sel / C_sel projection (N=16 each) ----------------------
__global__ void __launch_bounds__(256) proj_bc(
    const float* __restrict__ x, const float* __restrict__ WB, const float* __restrict__ WC)
{
    int m    = blockIdx.x * 8 + (threadIdx.x >> 5);
    int lane = threadIdx.x & 31;
    const float* W = (lane < 16) ? WB : WC;
    int n = lane & 15;
    const float* xr = x + (size_t)m * DM;
    float acc = 0.f;
#pragma unroll 2
    for (int d = 0; d < DM; d += 4) {
        float4 xv = *(const float4*)&xr[d];
        acc = fmaf(xv.x, W[(d+0)*SD + n], acc);
        acc = fmaf(xv.y, W[(d+1)*SD + n], acc);
        acc = fmaf(xv.z, W[(d+2)*SD + n], acc);
        acc = fmaf(xv.w, W[(d+3)*SD + n], acc);
    }
    float* out = (lane < 16) ? g_Bsel : g_Csel;
    out[(size_t)m * SD + n] = acc;
}

// ---------------- selective scan -------------------------------------------
// block = 256 threads = 16 groups of 16 lanes; group g handles (b, d0+g), lane = state n.
#define TC 128
__global__ void __launch_bounds__(256) scan_kernel(
    const float* __restrict__ x, const float* __restrict__ A_log)
{
    int blk = blockIdx.x;            // 128 blocks
    int b   = blk >> 6;              // 64 blocks per batch
    int d0  = (blk & 63) << 4;
    int tid = threadIdx.x;
    int g   = tid >> 4;
    int n   = tid & 15;
    int d   = d0 + g;

    __shared__ float s_delta[TC][16];
    __shared__ float s_x    [TC][16];
    __shared__ float s_B    [TC][16];
    __shared__ float s_C    [TC][16];
    __shared__ float s_y    [TC][16];

    float a = -__expf(A_log[d * SD + n]);
    float h = 0.f;

    const float* dbase = g_delta + ((size_t)b * SEQ) * DM + d0;
    const float* xbase = x       + ((size_t)b * SEQ) * DM + d0;
    const float* Bbase = g_Bsel  + ((size_t)b * SEQ) * SD;
    const float* Cbase = g_Csel  + ((size_t)b * SEQ) * SD;
    float*       ybase = g_ssm   + ((size_t)b * SEQ) * DM + d0;

    int lr = tid >> 4, lc = tid & 15;   // cooperative load coords

    for (int t0 = 0; t0 < SEQ; t0 += TC) {
        __syncthreads();   // previous store phase done before rewriting smem
        for (int r = lr; r < TC; r += 16) {
            s_delta[r][lc] = dbase[(size_t)(t0 + r) * DM + lc];
            s_x[r][lc]     = xbase[(size_t)(t0 + r) * DM + lc];
            s_B[r][lc]     = Bbase[(size_t)(t0 + r) * SD + lc];
            s_C[r][lc]     = Cbase[(size_t)(t0 + r) * SD + lc];
        }
        __syncthreads();
#pragma unroll 4
        for (int t = 0; t < TC; t++) {
            float dt = s_delta[t][g];
            float xv = s_x[t][g];
            float bn = s_B[t][n];
            float cn = s_C[t][n];
            float decay = __expf(dt * a);
            h = fmaf(h, decay, dt * xv * bn);
            float p = h * cn;
            p += __shfl_xor_sync(0xffffffffu, p, 8);
            p += __shfl_xor_sync(0xffffffffu, p, 4);
            p += __shfl_xor_sync(0xffffffffu, p, 2);
            p += __shfl_xor_sync(0xffffffffu, p, 1);
            if (n == 0) s_y[t][g] = p;
        }
        __syncthreads();
        for (int r = lr; r < TC; r += 16)
            ybase[(size_t)(t0 + r) * DM + lc] = s_y[r][lc];
    }
}

// ---------------- layernorm (in-place) + h_final capture --------------------
__global__ void __launch_bounds__(256) ln_kernel(
    const float* __restrict__ gamma, const float* __restrict__ beta)
{
    int m = blockIdx.x;
    float* row = g_ssm + (size_t)m * DM;
    int tid = threadIdx.x;
    float4 v = *(float4*)&row[tid * 4];
    float s  = v.x + v.y + v.z + v.w;
    float ss = v.x*v.x + v.y*v.y + v.z*v.z + v.w*v.w;
#pragma unroll
    for (int o = 16; o > 0; o >>= 1) {
        s  += __shfl_xor_sync(0xffffffffu, s,  o);
        ss += __shfl_xor_sync(0xffffffffu, ss, o);
    }
    __shared__ float rs[8], rss[8];
    if ((tid & 31) == 0) { rs[tid >> 5] = s; rss[tid >> 5] = ss; }
    __syncthreads();
    s = 0.f; ss = 0.f;
#pragma unroll
    for (int i = 0; i < 8; i++) { s += rs[i]; ss += rss[i]; }
    float mu  = s * (1.0f / DM);
    float var = ss * (1.0f / DM) - mu * mu;
    float inv = rsqrtf(var + 1e-5f);
    float4 g4 = *(const float4*)&gamma[tid * 4];
    float4 b4 = *(const float4*)&beta[tid * 4];
    v.x = (v.x - mu) * inv * g4.x + b4.x;
    v.y = (v.y - mu) * inv * g4.y + b4.y;
    v.z = (v.z - mu) * inv * g4.z + b4.z;
    v.w = (v.w - mu) * inv * g4.w + b4.w;
    *(float4*)&row[tid * 4] = v;
    if ((m & (SEQ - 1)) == SEQ - 1) {
        int b = m / SEQ;
        *(float4*)&g_hfinal[b * DM + tid * 4] = v;
    }
}

// ---------------- h_proj = h_final @ W_imp ----------------------------------
__global__ void __launch_bounds__(256) hproj_kernel(const float* __restrict__ Wimp)
{
    int b = blockIdx.y;
    int j = blockIdx.x * 256 + threadIdx.x;
    __shared__ float hf[DM];
    for (int i = threadIdx.x; i < DM; i += 256) hf[i] = g_hfinal[b * DM + i];
    __syncthreads();
    float acc = 0.f;
#pragma unroll 8
    for (int d = 0; d < DM; d++)
        acc = fmaf(hf[d], Wimp[(size_t)d * DM + j], acc);
    g_hproj[b * DM + j] = acc;
}

// ---------------- raw_importance = einsum('bsd,bd->bs') ---------------------
__global__ void __launch_bounds__(256) raw_kernel(
    const float* __restrict__ x, float* __restrict__ out_raw)
{
    int m    = (blockIdx.x * 256 + threadIdx.x) >> 5;
    int lane = threadIdx.x & 31;
    int b    = m >> 12;
    const float* xr = x + (size_t)m * DM;
    const float* hp = g_hproj + b * DM;
    float acc = 0.f;
    for (int d = lane * 4; d < DM; d += 128) {
        float4 xv = *(const float4*)&xr[d];
        float4 hv = *(const float4*)&hp[d];
        acc += xv.x*hv.x + xv.y*hv.y + xv.z*hv.z + xv.w*hv.w;
    }
#pragma unroll
    for (int o = 16; o > 0; o >>= 1) acc += __shfl_xor_sync(0xffffffffu, acc, o);
    if (lane == 0) { g_raw[m] = acc; out_raw[m] = acc; }
}

// ---------------- softmax over seq (temp 0.5 -> *2) --------------------------
__global__ void __launch_bounds__(1024) softmax_kernel(float* __restrict__ out_imp)
{
    int b   = blockIdx.x;
    int tid = threadIdx.x;
    const float* r = g_raw + (size_t)b * SEQ;
    float4 rv = *(const float4*)&r[tid * 4];
    float v0 = rv.x * 2.0f, v1 = rv.y * 2.0f, v2 = rv.z * 2.0f, v3 = rv.w * 2.0f;
    float mx = fmaxf(fmaxf(v0, v1), fmaxf(v2, v3));

    __shared__ float swarp[32];
    __shared__ float bval;
#pragma unroll
    for (int o = 16; o > 0; o >>= 1) mx = fmaxf(mx, __shfl_xor_sync(0xffffffffu, mx, o));
    if ((tid & 31) == 0) swarp[tid >> 5] = mx;
    __syncthreads();
    if (tid < 32) {
        float v = swarp[tid];
#pragma unroll
        for (int o = 16; o > 0; o >>= 1) v = fmaxf(v, __shfl_xor_sync(0xffffffffu, v, o));
        if (tid == 0) bval = v;
    }
    __syncthreads();
    float gmax = bval;
    float e0 = __expf(v0 - gmax), e1 = __expf(v1 - gmax);
    float e2 = __expf(v2 - gmax), e3 = __expf(v3 - gmax);
    float sum = e0 + e1 + e2 + e3;
#pragma unroll
    for (int o = 16; o > 0; o >>= 1) sum += __shfl_xor_sync(0xffffffffu, sum, o);
    __syncthreads();   // swarp reuse
    if ((tid & 31) == 0) swarp[tid >> 5] = sum;
    __syncthreads();
    if (tid < 32) {
        float v = swarp[tid];
#pragma unroll
        for (int o = 16; o > 0; o >>= 1) v += __shfl_xor_sync(0xffffffffu, v, o);
        if (tid == 0) bval = v;
    }
    __syncthreads();
    float inv = 1.0f / bval;
    float4 o4; o4.x = e0 * inv; o4.y = e1 * inv; o4.z = e2 * inv; o4.w = e3 * inv;
    *(float4*)&out_imp[(size_t)b * SEQ + tid * 4] = o4;
}

// ---------------- launch ----------------------------------------------------
extern "C" void kernel_launch(void* const* d_in, const int* in_sizes, int n_in,
                              void* d_out, int out_size)
{
    const float* x       = (const float*)d_in[0];
    const float* A_log   = (const float*)d_in[1];
    const float* W_delta = (const float*)d_in[2];
    const float* W_B     = (const float*)d_in[3];
    const float* W_C     = (const float*)d_in[4];
    const float* gamma   = (const float*)d_in[5];
    const float* beta    = (const float*)d_in[6];
    const float* W_ctx   = (const float*)d_in[7];
    const float* scale   = (const float*)d_in[8];
    const float* W_imp   = (const float*)d_in[9];

    float* out     = (float*)d_out;
    float* out_imp = out;                                   // (2,4096)
    float* out_ctx = out + M_ROWS;                          // (2,4096,1024)
    float* out_raw = out + M_ROWS + (size_t)M_ROWS * DM;    // (2,4096)

    float *p_delta, *p_ssm;
    cudaGetSymbolAddress((void**)&p_delta, g_delta);
    cudaGetSymbolAddress((void**)&p_ssm,   g_ssm);

    dim3 gg(DM / 128, M_ROWS / 128);  // (8, 64)

    // delta = softplus(x @ W_delta)
    sgemm_epi<1><<<gg, 256>>>(x, W_delta, p_delta, M_ROWS, DM, DM, nullptr);
    // B_sel, C_sel
    proj_bc<<<M_ROWS / 8, 256>>>(x, W_B, W_C);
    // selective scan -> g_ssm (pre-LN)
    scan_kernel<<<128, 256>>>(x, A_log);
    // layernorm in-place + h_final
    ln_kernel<<<M_ROWS, 256>>>(gamma, beta);
    // h_proj = h_final @ W_imp
    hproj_kernel<<<dim3(DM / 256, BATCH), 256>>>(W_imp);
    // raw importance
    raw_kernel<<<M_ROWS / 8, 256>>>(x, out_raw);
    // softmax -> importance
    softmax_kernel<<<BATCH, 1024>>>(out_imp);
    // context = ln(ssm) @ W_ctx * scale
    sgemm_epi<0><<<gg, 256>>>(p_ssm, W_ctx, out_ctx, M_ROWS, DM, DM, scale);
}

// round 3
// speedup vs baseline: 1.5293x; 1.5293x over previous
#include <cuda_runtime.h>
#include <cuda_bf16.h>
#include <math.h>
#include <stdint.h>

#define BATCH 2
#define SEQ 4096
#define DM 1024
#define SD 16
#define M_ROWS (BATCH*SEQ)   // 8192
#define KBIG (3*DM)          // 3072: [hi | lo | hi] split-K

// ---------------- scratch (device globals; no allocations allowed) ----------
__device__ float g_delta[(size_t)M_ROWS * DM];
__device__ float g_Bsel [(size_t)M_ROWS * SD];
__device__ float g_Csel [(size_t)M_ROWS * SD];
__device__ float g_ssm  [(size_t)M_ROWS * DM];   // scan out (pre-LN)
__device__ float g_hfinal[BATCH * DM];
__device__ float g_hproj [BATCH * DM];
__device__ float g_raw  [M_ROWS];
__device__ __nv_bfloat16 g_xbig[(size_t)M_ROWS * KBIG];  // [xh | xl | xh]
__device__ __nv_bfloat16 g_sbig[(size_t)M_ROWS * KBIG];  // ln(ssm) splits
__device__ __nv_bfloat16 g_wd  [(size_t)KBIG * DM];      // [Wh; Wh; Wl]
__device__ __nv_bfloat16 g_wc  [(size_t)KBIG * DM];

// ---------------- PTX helpers ------------------------------------------------
__device__ __forceinline__ void ldsm_x4(uint32_t r[4], uint32_t addr) {
    asm volatile("ldmatrix.sync.aligned.m8n8.x4.shared.b16 {%0,%1,%2,%3}, [%4];\n"
        : "=r"(r[0]), "=r"(r[1]), "=r"(r[2]), "=r"(r[3]) : "r"(addr));
}
__device__ __forceinline__ void ldsm_x4_t(uint32_t r[4], uint32_t addr) {
    asm volatile("ldmatrix.sync.aligned.m8n8.x4.trans.shared.b16 {%0,%1,%2,%3}, [%4];\n"
        : "=r"(r[0]), "=r"(r[1]), "=r"(r[2]), "=r"(r[3]) : "r"(addr));
}
__device__ __forceinline__ void mma_bf16(float c[4], const uint32_t a[4],
                                         uint32_t b0, uint32_t b1) {
    asm volatile("mma.sync.aligned.m16n8k16.row.col.f32.bf16.bf16.f32 "
        "{%0,%1,%2,%3}, {%4,%5,%6,%7}, {%8,%9}, {%0,%1,%2,%3};\n"
        : "+f"(c[0]), "+f"(c[1]), "+f"(c[2]), "+f"(c[3])
        : "r"(a[0]), "r"(a[1]), "r"(a[2]), "r"(a[3]), "r"(b0), "r"(b1));
}
__device__ __forceinline__ void cp16(uint32_t saddr, const void* gaddr) {
    asm volatile("cp.async.cg.shared.global [%0], [%1], 16;\n" :: "r"(saddr), "l"(gaddr));
}

// ---------------- bf16-split tensor-core GEMM --------------------------------
// C[M x 1024] = A[M x 3072] @ B[3072 x 1024], fp32 acc.
// Block 128x128, BK=32, 8 warps (2x4), warp tile 64x32 via m16n8k16.
// EPI: 0 = *scale, 1 = softplus
template<int EPI>
__global__ void __launch_bounds__(256) mma_gemm(
    const __nv_bfloat16* __restrict__ A, const __nv_bfloat16* __restrict__ B,
    float* __restrict__ C, const float* __restrict__ scale_ptr)
{
    __shared__ __align__(16) __nv_bfloat16 As[2][128][40];   // pad 8
    __shared__ __align__(16) __nv_bfloat16 Bs[2][32][136];   // pad 8

    const int tid  = threadIdx.x;
    const int warp = tid >> 5, lane = tid & 31;
    const int wm = warp >> 2, wn = warp & 3;          // 2 x 4 warp grid
    const int brow = blockIdx.y * 128, bcol = blockIdx.x * 128;

    float acc[4][4][4];
#pragma unroll
    for (int i = 0; i < 4; i++)
#pragma unroll
        for (int j = 0; j < 4; j++)
#pragma unroll
            for (int c = 0; c < 4; c++) acc[i][j][c] = 0.f;

    const __nv_bfloat16* Ag = A + (size_t)brow * KBIG;
    const __nv_bfloat16* Bg = B + bcol;

    auto load_stage = [&](int s, int k0) {
#pragma unroll
        for (int i = 0; i < 2; i++) {                 // A: 128x32, 16B chunks
            int idx = tid + i * 256;
            int r = idx >> 2, sg = idx & 3;
            cp16((uint32_t)__cvta_generic_to_shared(&As[s][r][sg * 8]),
                 Ag + (size_t)r * KBIG + k0 + sg * 8);
        }
#pragma unroll
        for (int i = 0; i < 2; i++) {                 // B: 32x128
            int idx = tid + i * 256;
            int r = idx >> 4, sg = idx & 15;
            cp16((uint32_t)__cvta_generic_to_shared(&Bs[s][r][sg * 8]),
                 Bg + (size_t)(k0 + r) * DM + sg * 8);
        }
        asm volatile("cp.async.commit_group;\n");
    };

    load_stage(0, 0);
    asm volatile("cp.async.wait_group 0;\n");
    __syncthreads();

    const int NK = KBIG / 32;   // 96
    for (int kt = 0; kt < NK; kt++) {
        int cur = kt & 1;
        if (kt + 1 < NK) load_stage(cur ^ 1, (kt + 1) * 32);

#pragma unroll
        for (int kk = 0; kk < 32; kk += 16) {
            uint32_t af[4][4];
#pragma unroll
            for (int mt = 0; mt < 4; mt++) {
                uint32_t addr = (uint32_t)__cvta_generic_to_shared(
                    &As[cur][wm * 64 + mt * 16 + (lane & 15)][kk + (lane >> 4) * 8]);
                ldsm_x4(af[mt], addr);
            }
            uint32_t bf_[2][4];
#pragma unroll
            for (int np = 0; np < 2; np++) {
                uint32_t addr = (uint32_t)__cvta_generic_to_shared(
                    &Bs[cur][kk + (lane & 15)][wn * 32 + np * 16 + (lane >> 4) * 8]);
                ldsm_x4_t(bf_[np], addr);
            }
#pragma unroll
            for (int mt = 0; mt < 4; mt++)
#pragma unroll
                for (int nt = 0; nt < 4; nt++)
                    mma_bf16(acc[mt][nt], af[mt],
                             bf_[nt >> 1][(nt & 1) * 2], bf_[nt >> 1][(nt & 1) * 2 + 1]);
        }
        if (kt + 1 < NK) asm volatile("cp.async.wait_group 0;\n");
        __syncthreads();
    }

    float scl = 1.0f;
    if (EPI == 0 && scale_ptr) scl = *scale_ptr;
    const int g = lane >> 2, tg = lane & 3;
#pragma unroll
    for (int mt = 0; mt < 4; mt++) {
#pragma unroll
        for (int nt = 0; nt < 4; nt++) {
            int row = brow + wm * 64 + mt * 16 + g;
            int col = bcol + wn * 32 + nt * 8 + tg * 2;
            float v[4] = {acc[mt][nt][0], acc[mt][nt][1], acc[mt][nt][2], acc[mt][nt][3]};
#pragma unroll
            for (int c = 0; c < 4; c++) {
                if (EPI == 1) v[c] = fmaxf(v[c], 0.f) + log1pf(__expf(-fabsf(v[c])));
                else          v[c] *= scl;
            }
            *(float2*)&C[(size_t)row * DM + col]       = make_float2(v[0], v[1]);
            *(float2*)&C[(size_t)(row + 8) * DM + col] = make_float2(v[2], v[3]);
        }
    }
}

// ---------------- fp32 -> bf16 hi/lo split conversions ------------------------
__device__ __forceinline__ void split4(float4 v, uint2& hp, uint2& lp) {
    __nv_bfloat162 h01 = __floats2bfloat162_rn(v.x, v.y);
    __nv_bfloat162 h23 = __floats2bfloat162_rn(v.z, v.w);
    float lx = v.x - __bfloat162float(h01.x);
    float ly = v.y - __bfloat162float(h01.y);
    float lz = v.z - __bfloat162float(h23.x);
    float lw = v.w - __bfloat162float(h23.y);
    __nv_bfloat162 l01 = __floats2bfloat162_rn(lx, ly);
    __nv_bfloat162 l23 = __floats2bfloat162_rn(lz, lw);
    hp.x = *(uint32_t*)&h01; hp.y = *(uint32_t*)&h23;
    lp.x = *(uint32_t*)&l01; lp.y = *(uint32_t*)&l23;
}

__global__ void __launch_bounds__(256) convert_x(const float* __restrict__ x)
{
    int m = blockIdx.x, j = threadIdx.x * 4;
    float4 v = *(const float4*)&x[(size_t)m * DM + j];
    uint2 hp, lp; split4(v, hp, lp);
    size_t base = (size_t)m * KBIG + j;
    *(uint2*)&g_xbig[base]            = hp;
    *(uint2*)&g_xbig[base + DM]       = lp;
    *(uint2*)&g_xbig[base + 2 * DM]   = hp;
}

__global__ void __launch_bounds__(256) convert_w(
    const float* __restrict__ W, __nv_bfloat16* __restrict__ Wb)
{
    int i = blockIdx.x, j = threadIdx.x * 4;
    float4 v = *(const float4*)&W[(size_t)i * DM + j];
    uint2 hp, lp; split4(v, hp, lp);
    size_t o = (size_t)i * DM + j;
    *(uint2*)&Wb[o]                       = hp;
    *(uint2*)&Wb[o + (size_t)DM * DM]     = hp;
    *(uint2*)&Wb[o + (size_t)2 * DM * DM] = lp;
}

// ---------------- B_sel / C_sel projection (N=16 each) ----------------------
__global__ void __launch_bounds__(256) proj_bc(
    const float* __restrict__ x, const float* __restrict__ WB, const float* __restrict__ WC)
{
    int m    = blockIdx.x * 8 + (threadIdx.x >> 5);
    int lane = threadIdx.x & 31;
    const float* W = (lane < 16) ? WB : WC;
    int n = lane & 15;
    const float* xr = x + (size_t)m * DM;
    float acc = 0.f;
#pragma unroll 2
    for (int d = 0; d < DM; d += 4) {
        float4 xv = *(const float4*)&xr[d];
        acc = fmaf(xv.x, W[(d+0)*SD + n], acc);
        acc = fmaf(xv.y, W[(d+1)*SD + n], acc);
        acc = fmaf(xv.z, W[(d+2)*SD + n], acc);
        acc = fmaf(xv.w, W[(d+3)*SD + n], acc);
    }
    float* out = (lane < 16) ? g_Bsel : g_Csel;
    out[(size_t)m * SD + n] = acc;
}

// ---------------- selective scan ---------------------------------------------
#define TC 128
__global__ void __launch_bounds__(256) scan_kernel(
    const float* __restrict__ x, const float* __restrict__ A_log)
{
    int blk = blockIdx.x;
    int b   = blk >> 6;
    int d0  = (blk & 63) << 4;
    int tid = threadIdx.x;
    int g   = tid >> 4;
    int n   = tid & 15;
    int d   = d0 + g;

    __shared__ float s_delta[TC][16];
    __shared__ float s_x    [TC][16];
    __shared__ float s_B    [TC][16];
    __shared__ float s_C    [TC][16];
    __shared__ float s_y    [TC][16];

    float a = -__expf(A_log[d * SD + n]);
    float h = 0.f;

    const float* dbase = g_delta + ((size_t)b * SEQ) * DM + d0;
    const float* xbase = x       + ((size_t)b * SEQ) * DM + d0;
    const float* Bbase = g_Bsel  + ((size_t)b * SEQ) * SD;
    const float* Cbase = g_Csel  + ((size_t)b * SEQ) * SD;
    float*       ybase = g_ssm   + ((size_t)b * SEQ) * DM + d0;

    int lr = tid >> 4, lc = tid & 15;

    for (int t0 = 0; t0 < SEQ; t0 += TC) {
        __syncthreads();
        for (int r = lr; r < TC; r += 16) {
            s_delta[r][lc] = dbase[(size_t)(t0 + r) * DM + lc];
            s_x[r][lc]     = xbase[(size_t)(t0 + r) * DM + lc];
            s_B[r][lc]     = Bbase[(size_t)(t0 + r) * SD + lc];
            s_C[r][lc]     = Cbase[(size_t)(t0 + r) * SD + lc];
        }
        __syncthreads();
#pragma unroll 4
        for (int t = 0; t < TC; t++) {
            float dt = s_delta[t][g];
            float xv = s_x[t][g];
            float bn = s_B[t][n];
            float cn = s_C[t][n];
            float decay = __expf(dt * a);
            h = fmaf(h, decay, dt * xv * bn);
            float p = h * cn;
            p += __shfl_xor_sync(0xffffffffu, p, 8);
            p += __shfl_xor_sync(0xffffffffu, p, 4);
            p += __shfl_xor_sync(0xffffffffu, p, 2);
            p += __shfl_xor_sync(0xffffffffu, p, 1);
            if (n == 0) s_y[t][g] = p;
        }
        __syncthreads();
        for (int r = lr; r < TC; r += 16)
            ybase[(size_t)(t0 + r) * DM + lc] = s_y[r][lc];
    }
}

// ---------------- layernorm -> bf16 splits + h_final --------------------------
__global__ void __launch_bounds__(256) ln_kernel(
    const float* __restrict__ gamma, const float* __restrict__ beta)
{
    int m = blockIdx.x;
    const float* row = g_ssm + (size_t)m * DM;
    int tid = threadIdx.x;
    float4 v = *(const float4*)&row[tid * 4];
    float s  = v.x + v.y + v.z + v.w;
    float ss = v.x*v.x + v.y*v.y + v.z*v.z + v.w*v.w;
#pragma unroll
    for (int o = 16; o > 0; o >>= 1) {
        s  += __shfl_xor_sync(0xffffffffu, s,  o);
        ss += __shfl_xor_sync(0xffffffffu, ss, o);
    }
    __shared__ float rs[8], rss[8];
    if ((tid & 31) == 0) { rs[tid >> 5] = s; rss[tid >> 5] = ss; }
    __syncthreads();
    s = 0.f; ss = 0.f;
#pragma unroll
    for (int i = 0; i < 8; i++) { s += rs[i]; ss += rss[i]; }
    float mu  = s * (1.0f / DM);
    float var = ss * (1.0f / DM) - mu * mu;
    float inv = rsqrtf(var + 1e-5f);
    float4 g4 = *(const float4*)&gamma[tid * 4];
    float4 b4 = *(const float4*)&beta[tid * 4];
    v.x = (v.x - mu) * inv * g4.x + b4.x;
    v.y = (v.y - mu) * inv * g4.y + b4.y;
    v.z = (v.z - mu) * inv * g4.z + b4.z;
    v.w = (v.w - mu) * inv * g4.w + b4.w;

    uint2 hp, lp; split4(v, hp, lp);
    size_t base = (size_t)m * KBIG + tid * 4;
    *(uint2*)&g_sbig[base]          = hp;
    *(uint2*)&g_sbig[base + DM]     = lp;
    *(uint2*)&g_sbig[base + 2*DM]   = hp;

    if ((m & (SEQ - 1)) == SEQ - 1) {
        int b = m / SEQ;
        *(float4*)&g_hfinal[b * DM + tid * 4] = v;
    }
}

// ---------------- h_proj = h_final @ W_imp ------------------------------------
__global__ void __launch_bounds__(256) hproj_kernel(const float* __restrict__ Wimp)
{
    int b = blockIdx.y;
    int j = blockIdx.x * 256 + threadIdx.x;
    __shared__ float hf[DM];
    for (int i = threadIdx.x; i < DM; i += 256) hf[i] = g_hfinal[b * DM + i];
    __syncthreads();
    float acc = 0.f;
#pragma unroll 8
    for (int d = 0; d < DM; d++)
        acc = fmaf(hf[d], Wimp[(size_t)d * DM + j], acc);
    g_hproj[b * DM + j] = acc;
}

// ---------------- raw_importance = einsum('bsd,bd->bs') -----------------------
__global__ void __launch_bounds__(256) raw_kernel(
    const float* __restrict__ x, float* __restrict__ out_raw)
{
    int m    = (blockIdx.x * 256 + threadIdx.x) >> 5;
    int lane = threadIdx.x & 31;
    int b    = m >> 12;
    const float* xr = x + (size_t)m * DM;
    const float* hp = g_hproj + b * DM;
    float acc = 0.f;
    for (int d = lane * 4; d < DM; d += 128) {
        float4 xv = *(const float4*)&xr[d];
        float4 hv = *(const float4*)&hp[d];
        acc += xv.x*hv.x + xv.y*hv.y + xv.z*hv.z + xv.w*hv.w;
    }
#pragma unroll
    for (int o = 16; o > 0; o >>= 1) acc += __shfl_xor_sync(0xffffffffu, acc, o);
    if (lane == 0) { g_raw[m] = acc; out_raw[m] = acc; }
}

// ---------------- softmax over seq (temp 0.5 -> *2) ----------------------------
__global__ void __launch_bounds__(1024) softmax_kernel(float* __restrict__ out_imp)
{
    int b   = blockIdx.x;
    int tid = threadIdx.x;
    const float* r = g_raw + (size_t)b * SEQ;
    float4 rv = *(const float4*)&r[tid * 4];
    float v0 = rv.x * 2.0f, v1 = rv.y * 2.0f, v2 = rv.z * 2.0f, v3 = rv.w * 2.0f;
    float mx = fmaxf(fmaxf(v0, v1), fmaxf(v2, v3));

    __shared__ float swarp[32];
    __shared__ float bval;
#pragma unroll
    for (int o = 16; o > 0; o >>= 1) mx = fmaxf(mx, __shfl_xor_sync(0xffffffffu, mx, o));
    if ((tid & 31) == 0) swarp[tid >> 5] = mx;
    __syncthreads();
    if (tid < 32) {
        float v = swarp[tid];
#pragma unroll
        for (int o = 16; o > 0; o >>= 1) v = fmaxf(v, __shfl_xor_sync(0xffffffffu, v, o));
        if (tid == 0) bval = v;
    }
    __syncthreads();
    float gmax = bval;
    float e0 = __expf(v0 - gmax), e1 = __expf(v1 - gmax);
    float e2 = __expf(v2 - gmax), e3 = __expf(v3 - gmax);
    float sum = e0 + e1 + e2 + e3;
#pragma unroll
    for (int o = 16; o > 0; o >>= 1) sum += __shfl_xor_sync(0xffffffffu, sum, o);
    __syncthreads();
    if ((tid & 31) == 0) swarp[tid >> 5] = sum;
    __syncthreads();
    if (tid < 32) {
        float v = swarp[tid];
#pragma unroll
        for (int o = 16; o > 0; o >>= 1) v += __shfl_xor_sync(0xffffffffu, v, o);
        if (tid == 0) bval = v;
    }
    __syncthreads();
    float inv = 1.0f / bval;
    float4 o4; o4.x = e0 * inv; o4.y = e1 * inv; o4.z = e2 * inv; o4.w = e3 * inv;
    *(float4*)&out_imp[(size_t)b * SEQ + tid * 4] = o4;
}

// ---------------- launch -------------------------------------------------------
extern "C" void kernel_launch(void* const* d_in, const int* in_sizes, int n_in,
                              void* d_out, int out_size)
{
    const float* x       = (const float*)d_in[0];
    const float* A_log   = (const float*)d_in[1];
    const float* W_delta = (const float*)d_in[2];
    const float* W_B     = (const float*)d_in[3];
    const float* W_C     = (const float*)d_in[4];
    const float* gamma   = (const float*)d_in[5];
    const float* beta    = (const float*)d_in[6];
    const float* W_ctx   = (const float*)d_in[7];
    const float* scale   = (const float*)d_in[8];
    const float* W_imp   = (const float*)d_in[9];

    float* out     = (float*)d_out;
    float* out_imp = out;
    float* out_ctx = out + M_ROWS;
    float* out_raw = out + M_ROWS + (size_t)M_ROWS * DM;

    float *p_delta;
    __nv_bfloat16 *p_xbig, *p_sbig, *p_wd, *p_wc;
    cudaGetSymbolAddress((void**)&p_delta, g_delta);
    cudaGetSymbolAddress((void**)&p_xbig,  g_xbig);
    cudaGetSymbolAddress((void**)&p_sbig,  g_sbig);
    cudaGetSymbolAddress((void**)&p_wd,    g_wd);
    cudaGetSymbolAddress((void**)&p_wc,    g_wc);

    dim3 gg(DM / 128, M_ROWS / 128);   // (8, 64)

    convert_x<<<M_ROWS, 256>>>(x);
    convert_w<<<DM, 256>>>(W_delta, p_wd);
    convert_w<<<DM, 256>>>(W_ctx,   p_wc);

    // delta = softplus(x @ W_delta)   (tensor cores, bf16 split)
    mma_gemm<1><<<gg, 256>>>(p_xbig, p_wd, p_delta, nullptr);

    proj_bc<<<M_ROWS / 8, 256>>>(x, W_B, W_C);
    scan_kernel<<<128, 256>>>(x, A_log);
    ln_kernel<<<M_ROWS, 256>>>(gamma, beta);

    hproj_kernel<<<dim3(DM / 256, BATCH), 256>>>(W_imp);
    raw_kernel<<<M_ROWS / 8, 256>>>(x, out_raw);
    softmax_kernel<<<BATCH, 1024>>>(out_imp);

    // context = ln(ssm) @ W_ctx * scale   (tensor cores, bf16 split)
    mma_gemm<0><<<gg, 256>>>(p_sbig, p_wc, out_ctx, scale);
}

// round 4
// speedup vs baseline: 2.1919x; 1.4332x over previous
#include <cuda_runtime.h>
#include <cuda_bf16.h>
#include <math.h>
#include <stdint.h>

#define BATCH 2
#define SEQ 4096
#define DM 1024
#define SD 16
#define M_ROWS (BATCH*SEQ)   // 8192
#define KBIG (3*DM)          // 3072: [hi | lo | hi] split-K
#define NB1 1152             // GEMM1 padded N (1024 delta + 16 B + 16 C + 96 pad)
#define NCH 16               // scan chunks
#define CHL (SEQ/NCH)        // 256 steps per chunk

// ---------------- scratch (device globals; no allocations allowed) ----------
__device__ float g_delta[(size_t)M_ROWS * DM];
__device__ float g_Bsel [(size_t)M_ROWS * SD];
__device__ float g_Csel [(size_t)M_ROWS * SD];
__device__ float g_ssm  [(size_t)M_ROWS * DM];
__device__ float g_hfinal[BATCH * DM];
__device__ float g_hproj [BATCH * DM];
__device__ float g_raw  [M_ROWS];
__device__ float g_hchunk[(size_t)BATCH * NCH * DM * SD];  // F per chunk
__device__ float g_hinit [(size_t)BATCH * NCH * DM * SD];  // corrected h0
__device__ float g_sumdel[(size_t)BATCH * NCH * DM];       // sum delta per chunk
__device__ __nv_bfloat16 g_xbig [(size_t)M_ROWS * KBIG];   // [xh | xl | xh]
__device__ __nv_bfloat16 g_sbig [(size_t)M_ROWS * KBIG];   // ln(ssm) splits
__device__ __nv_bfloat16 g_wcomb[(size_t)KBIG * NB1];      // [Wd|WB|WC|0] x {h,h,l}
__device__ __nv_bfloat16 g_wc   [(size_t)KBIG * DM];       // W_ctx splits

// ---------------- PTX helpers ------------------------------------------------
__device__ __forceinline__ void ldsm_x4(uint32_t r[4], uint32_t addr) {
    asm volatile("ldmatrix.sync.aligned.m8n8.x4.shared.b16 {%0,%1,%2,%3}, [%4];\n"
        : "=r"(r[0]), "=r"(r[1]), "=r"(r[2]), "=r"(r[3]) : "r"(addr));
}
__device__ __forceinline__ void ldsm_x4_t(uint32_t r[4], uint32_t addr) {
    asm volatile("ldmatrix.sync.aligned.m8n8.x4.trans.shared.b16 {%0,%1,%2,%3}, [%4];\n"
        : "=r"(r[0]), "=r"(r[1]), "=r"(r[2]), "=r"(r[3]) : "r"(addr));
}
__device__ __forceinline__ void mma_bf16(float c[4], const uint32_t a[4],
                                         uint32_t b0, uint32_t b1) {
    asm volatile("mma.sync.aligned.m16n8k16.row.col.f32.bf16.bf16.f32 "
        "{%0,%1,%2,%3}, {%4,%5,%6,%7}, {%8,%9}, {%0,%1,%2,%3};\n"
        : "+f"(c[0]), "+f"(c[1]), "+f"(c[2]), "+f"(c[3])
        : "r"(a[0]), "r"(a[1]), "r"(a[2]), "r"(a[3]), "r"(b0), "r"(b1));
}
__device__ __forceinline__ void cp16(uint32_t saddr, const void* gaddr) {
    asm volatile("cp.async.cg.shared.global [%0], [%1], 16;\n" :: "r"(saddr), "l"(gaddr));
}

// ---------------- bf16-split tensor-core GEMM --------------------------------
// MODE 0: C = A@B * scale (N=1024). MODE 1: merged delta/B_sel/C_sel (N=NB1).
template<int MODE>
__global__ void __launch_bounds__(256) mma_gemm(
    const __nv_bfloat16* __restrict__ A, const __nv_bfloat16* __restrict__ B,
    float* __restrict__ C, const float* __restrict__ scale_ptr, int NBr)
{
    __shared__ __align__(16) __nv_bfloat16 As[2][128][40];
    __shared__ __align__(16) __nv_bfloat16 Bs[2][32][136];

    const int tid  = threadIdx.x;
    const int warp = tid >> 5, lane = tid & 31;
    const int wm = warp >> 2, wn = warp & 3;
    const int brow = blockIdx.y * 128, bcol = blockIdx.x * 128;

    float acc[4][4][4];
#pragma unroll
    for (int i = 0; i < 4; i++)
#pragma unroll
        for (int j = 0; j < 4; j++)
#pragma unroll
            for (int c = 0; c < 4; c++) acc[i][j][c] = 0.f;

    const __nv_bfloat16* Ag = A + (size_t)brow * KBIG;
    const __nv_bfloat16* Bg = B + bcol;

    auto load_stage = [&](int s, int k0) {
#pragma unroll
        for (int i = 0; i < 2; i++) {
            int idx = tid + i * 256;
            int r = idx >> 2, sg = idx & 3;
            cp16((uint32_t)__cvta_generic_to_shared(&As[s][r][sg * 8]),
                 Ag + (size_t)r * KBIG + k0 + sg * 8);
        }
#pragma unroll
        for (int i = 0; i < 2; i++) {
            int idx = tid + i * 256;
            int r = idx >> 4, sg = idx & 15;
            cp16((uint32_t)__cvta_generic_to_shared(&Bs[s][r][sg * 8]),
                 Bg + (size_t)(k0 + r) * NBr + sg * 8);
        }
        asm volatile("cp.async.commit_group;\n");
    };

    load_stage(0, 0);
    asm volatile("cp.async.wait_group 0;\n");
    __syncthreads();

    const int NK = KBIG / 32;   // 96
    for (int kt = 0; kt < NK; kt++) {
        int cur = kt & 1;
        if (kt + 1 < NK) load_stage(cur ^ 1, (kt + 1) * 32);

#pragma unroll
        for (int kk = 0; kk < 32; kk += 16) {
            uint32_t af[4][4];
#pragma unroll
            for (int mt = 0; mt < 4; mt++) {
                uint32_t addr = (uint32_t)__cvta_generic_to_shared(
                    &As[cur][wm * 64 + mt * 16 + (lane & 15)][kk + (lane >> 4) * 8]);
                ldsm_x4(af[mt], addr);
            }
            uint32_t bf_[2][4];
#pragma unroll
            for (int np = 0; np < 2; np++) {
                uint32_t addr = (uint32_t)__cvta_generic_to_shared(
                    &Bs[cur][kk + (lane & 15)][wn * 32 + np * 16 + (lane >> 4) * 8]);
                ldsm_x4_t(bf_[np], addr);
            }
#pragma unroll
            for (int mt = 0; mt < 4; mt++)
#pragma unroll
                for (int nt = 0; nt < 4; nt++)
                    mma_bf16(acc[mt][nt], af[mt],
                             bf_[nt >> 1][(nt & 1) * 2], bf_[nt >> 1][(nt & 1) * 2 + 1]);
        }
        if (kt + 1 < NK) asm volatile("cp.async.wait_group 0;\n");
        __syncthreads();
    }

    float scl = 1.0f;
    if (MODE == 0 && scale_ptr) scl = *scale_ptr;
    const int g = lane >> 2, tg = lane & 3;
#pragma unroll
    for (int mt = 0; mt < 4; mt++) {
#pragma unroll
        for (int nt = 0; nt < 4; nt++) {
            int col = bcol + wn * 32 + nt * 8 + tg * 2;
#pragma unroll
            for (int half = 0; half < 2; half++) {
                int row = brow + wm * 64 + mt * 16 + g + half * 8;
                float v0 = acc[mt][nt][half * 2], v1 = acc[mt][nt][half * 2 + 1];
                if (MODE == 0) {
                    *(float2*)&C[(size_t)row * DM + col] = make_float2(v0 * scl, v1 * scl);
                } else {
                    if (col < DM) {
                        v0 = fmaxf(v0, 0.f) + log1pf(__expf(-fabsf(v0)));
                        v1 = fmaxf(v1, 0.f) + log1pf(__expf(-fabsf(v1)));
                        *(float2*)&C[(size_t)row * DM + col] = make_float2(v0, v1);
                    } else if (col < DM + SD) {
                        *(float2*)&g_Bsel[(size_t)row * SD + col - DM] = make_float2(v0, v1);
                    } else if (col < DM + 2 * SD) {
                        *(float2*)&g_Csel[(size_t)row * SD + col - DM - SD] = make_float2(v0, v1);
                    }
                }
            }
        }
    }
}

// ---------------- fp32 -> bf16 hi/lo split conversions ------------------------
__device__ __forceinline__ void split4(float4 v, uint2& hp, uint2& lp) {
    __nv_bfloat162 h01 = __floats2bfloat162_rn(v.x, v.y);
    __nv_bfloat162 h23 = __floats2bfloat162_rn(v.z, v.w);
    float lx = v.x - __bfloat162float(h01.x);
    float ly = v.y - __bfloat162float(h01.y);
    float lz = v.z - __bfloat162float(h23.x);
    float lw = v.w - __bfloat162float(h23.y);
    __nv_bfloat162 l01 = __floats2bfloat162_rn(lx, ly);
    __nv_bfloat162 l23 = __floats2bfloat162_rn(lz, lw);
    hp.x = *(uint32_t*)&h01; hp.y = *(uint32_t*)&h23;
    lp.x = *(uint32_t*)&l01; lp.y = *(uint32_t*)&l23;
}

__global__ void __launch_bounds__(256) convert_x(const float* __restrict__ x)
{
    int m = blockIdx.x, j = threadIdx.x * 4;
    float4 v = *(const float4*)&x[(size_t)m * DM + j];
    uint2 hp, lp; split4(v, hp, lp);
    size_t base = (size_t)m * KBIG + j;
    *(uint2*)&g_xbig[base]          = hp;
    *(uint2*)&g_xbig[base + DM]     = lp;
    *(uint2*)&g_xbig[base + 2*DM]   = hp;
}

// W_delta -> g_wcomb cols [0,1024), rows {r:hi, r+1024:hi, r+2048:lo}
__global__ void __launch_bounds__(256) convert_wd(const float* __restrict__ W)
{
    int i = blockIdx.x, j = threadIdx.x * 4;
    float4 v = *(const float4*)&W[(size_t)i * DM + j];
    uint2 hp, lp; split4(v, hp, lp);
    *(uint2*)&g_wcomb[(size_t)i * NB1 + j]            = hp;
    *(uint2*)&g_wcomb[(size_t)(i + DM) * NB1 + j]     = hp;
    *(uint2*)&g_wcomb[(size_t)(i + 2*DM) * NB1 + j]   = lp;
}

// W_B / W_C -> g_wcomb cols [1024,1152) (pad cols zeroed)
__global__ void __launch_bounds__(128) convert_wbc(
    const float* __restrict__ WB, const float* __restrict__ WC)
{
    int r = blockIdx.x;           // 0..KBIG-1
    int t = threadIdx.x;          // 0..127
    int srcrow = r & (DM - 1);
    bool lo = (r >= 2 * DM);
    float v = 0.f;
    if (t < SD) v = WB[srcrow * SD + t];
    else if (t < 2 * SD) v = WC[srcrow * SD + t - SD];
    __nv_bfloat16 hv = __float2bfloat16(v);
    __nv_bfloat16 res = lo ? __float2bfloat16(v - __bfloat162float(hv)) : hv;
    if (t >= 2 * SD) res = __float2bfloat16(0.f);
    g_wcomb[(size_t)r * NB1 + DM + t] = res;
}

__global__ void __launch_bounds__(256) convert_wc(const float* __restrict__ W)
{
    int i = blockIdx.x, j = threadIdx.x * 4;
    float4 v = *(const float4*)&W[(size_t)i * DM + j];
    uint2 hp, lp; split4(v, hp, lp);
    size_t o = (size_t)i * DM + j;
    *(uint2*)&g_wc[o]                       = hp;
    *(uint2*)&g_wc[o + (size_t)DM * DM]     = hp;
    *(uint2*)&g_wc[o + (size_t)2 * DM * DM] = lp;
}

// ---------------- chunked selective scan ---------------------------------------
#define TC 128
// Pass 1: local scan from h=0 per chunk; emit final h (F) and sum(delta) (S).
__global__ void __launch_bounds__(256) scan_pass1(
    const float* __restrict__ x, const float* __restrict__ A_log)
{
    int blk  = blockIdx.x;               // 2048 = b(2) * dblk(64) * c(16)
    int c    = blk & (NCH - 1);
    int dblk = (blk >> 4) & 63;
    int b    = blk >> 10;
    int tid  = threadIdx.x;
    int g    = tid >> 4, n = tid & 15;
    int d0   = dblk << 4, d = d0 + g;

    __shared__ float s_delta[TC][16];
    __shared__ float s_x    [TC][16];
    __shared__ float s_B    [TC][16];

    float a = -__expf(A_log[d * SD + n]);
    float h = 0.f, sdt = 0.f;

    const float* dbase = g_delta + ((size_t)b * SEQ) * DM + d0;
    const float* xbase = x       + ((size_t)b * SEQ) * DM + d0;
    const float* Bbase = g_Bsel  + ((size_t)b * SEQ) * SD;
    int lr = tid >> 4, lc = tid & 15;
    int tstart = c * CHL;

    for (int t0 = tstart; t0 < tstart + CHL; t0 += TC) {
        __syncthreads();
        for (int r = lr; r < TC; r += 16) {
            s_delta[r][lc] = dbase[(size_t)(t0 + r) * DM + lc];
            s_x[r][lc]     = xbase[(size_t)(t0 + r) * DM + lc];
            s_B[r][lc]     = Bbase[(size_t)(t0 + r) * SD + lc];
        }
        __syncthreads();
#pragma unroll 8
        for (int t = 0; t < TC; t++) {
            float dt = s_delta[t][g];
            float xv = s_x[t][g];
            float bn = s_B[t][n];
            h = fmaf(h, __expf(dt * a), dt * xv * bn);
            sdt += dt;
        }
    }
    size_t ci = ((size_t)(b * NCH + c) * DM + d) * SD + n;
    g_hchunk[ci] = h;
    if (n == 0) g_sumdel[(size_t)(b * NCH + c) * DM + d] = sdt;
}

// Pass 2: sequential chunk recombination -> h0 per chunk.
__global__ void __launch_bounds__(256) scan_pass2(const float* __restrict__ A_log)
{
    int idx = blockIdx.x * 256 + threadIdx.x;   // 32768
    int n = idx & 15, d = (idx >> 4) & (DM - 1), b = idx >> 14;
    float a = -__expf(A_log[d * SD + n]);
    float H = 0.f;
#pragma unroll
    for (int c = 0; c < NCH; c++) {
        size_t ci = ((size_t)(b * NCH + c) * DM + d) * SD + n;
        g_hinit[ci] = H;
        float S = g_sumdel[(size_t)(b * NCH + c) * DM + d];
        H = __expf(a * S) * H + g_hchunk[ci];
    }
}

// Pass 3: re-scan chunk with corrected h0; emit y.
__global__ void __launch_bounds__(256) scan_pass3(
    const float* __restrict__ x, const float* __restrict__ A_log)
{
    int blk  = blockIdx.x;
    int c    = blk & (NCH - 1);
    int dblk = (blk >> 4) & 63;
    int b    = blk >> 10;
    int tid  = threadIdx.x;
    int g    = tid >> 4, n = tid & 15;
    int d0   = dblk << 4, d = d0 + g;

    __shared__ float s_delta[TC][16];
    __shared__ float s_x    [TC][16];
    __shared__ float s_B    [TC][16];
    __shared__ float s_C    [TC][16];
    __shared__ float s_y    [TC][16];

    float a = -__expf(A_log[d * SD + n]);
    float h = g_hinit[((size_t)(b * NCH + c) * DM + d) * SD + n];

    const float* dbase = g_delta + ((size_t)b * SEQ) * DM + d0;
    const float* xbase = x       + ((size_t)b * SEQ) * DM + d0;
    const float* Bbase = g_Bsel  + ((size_t)b * SEQ) * SD;
    const float* Cbase = g_Csel  + ((size_t)b * SEQ) * SD;
    float*       ybase = g_ssm   + ((size_t)b * SEQ) * DM + d0;
    int lr = tid >> 4, lc = tid & 15;
    int tstart = c * CHL;

    for (int t0 = tstart; t0 < tstart + CHL; t0 += TC) {
        __syncthreads();
        for (int r = lr; r < TC; r += 16) {
            s_delta[r][lc] = dbase[(size_t)(t0 + r) * DM + lc];
            s_x[r][lc]     = xbase[(size_t)(t0 + r) * DM + lc];
            s_B[r][lc]     = Bbase[(size_t)(t0 + r) * SD + lc];
            s_C[r][lc]     = Cbase[(size_t)(t0 + r) * SD + lc];
        }
        __syncthreads();
#pragma unroll 4
        for (int t = 0; t < TC; t++) {
            float dt = s_delta[t][g];
            float xv = s_x[t][g];
            float bn = s_B[t][n];
            float cn = s_C[t][n];
            h = fmaf(h, __expf(dt * a), dt * xv * bn);
            float p = h * cn;
            p += __shfl_xor_sync(0xffffffffu, p, 8);
            p += __shfl_xor_sync(0xffffffffu, p, 4);
            p += __shfl_xor_sync(0xffffffffu, p, 2);
            p += __shfl_xor_sync(0xffffffffu, p, 1);
            if (n == 0) s_y[t][g] = p;
        }
        __syncthreads();
        for (int r = lr; r < TC; r += 16)
            ybase[(size_t)(t0 + r) * DM + lc] = s_y[r][lc];
    }
}

// ---------------- layernorm -> bf16 splits + h_final --------------------------
__global__ void __launch_bounds__(256) ln_kernel(
    const float* __restrict__ gamma, const float* __restrict__ beta)
{
    int m = blockIdx.x;
    const float* row = g_ssm + (size_t)m * DM;
    int tid = threadIdx.x;
    float4 v = *(const float4*)&row[tid * 4];
    float s  = v.x + v.y + v.z + v.w;
    float ss = v.x*v.x + v.y*v.y + v.z*v.z + v.w*v.w;
#pragma unroll
    for (int o = 16; o > 0; o >>= 1) {
        s  += __shfl_xor_sync(0xffffffffu, s,  o);
        ss += __shfl_xor_sync(0xffffffffu, ss, o);
    }
    __shared__ float rs[8], rss[8];
    if ((tid & 31) == 0) { rs[tid >> 5] = s; rss[tid >> 5] = ss; }
    __syncthreads();
    s = 0.f; ss = 0.f;
#pragma unroll
    for (int i = 0; i < 8; i++) { s += rs[i]; ss += rss[i]; }
    float mu  = s * (1.0f / DM);
    float var = ss * (1.0f / DM) - mu * mu;
    float inv = rsqrtf(var + 1e-5f);
    float4 g4 = *(const float4*)&gamma[tid * 4];
    float4 b4 = *(const float4*)&beta[tid * 4];
    v.x = (v.x - mu) * inv * g4.x + b4.x;
    v.y = (v.y - mu) * inv * g4.y + b4.y;
    v.z = (v.z - mu) * inv * g4.z + b4.z;
    v.w = (v.w - mu) * inv * g4.w + b4.w;

    uint2 hp, lp; split4(v, hp, lp);
    size_t base = (size_t)m * KBIG + tid * 4;
    *(uint2*)&g_sbig[base]          = hp;
    *(uint2*)&g_sbig[base + DM]     = lp;
    *(uint2*)&g_sbig[base + 2*DM]   = hp;

    if ((m & (SEQ - 1)) == SEQ - 1) {
        int b = m / SEQ;
        *(float4*)&g_hfinal[b * DM + tid * 4] = v;
    }
}

// ---------------- h_proj = h_final @ W_imp ------------------------------------
__global__ void __launch_bounds__(256) hproj_kernel(const float* __restrict__ Wimp)
{
    int b = blockIdx.y;
    int j = blockIdx.x * 256 + threadIdx.x;
    __shared__ float hf[DM];
    for (int i = threadIdx.x; i < DM; i += 256) hf[i] = g_hfinal[b * DM + i];
    __syncthreads();
    float acc = 0.f;
#pragma unroll 8
    for (int d = 0; d < DM; d++)
        acc = fmaf(hf[d], Wimp[(size_t)d * DM + j], acc);
    g_hproj[b * DM + j] = acc;
}

// ---------------- raw_importance ------------------------------------------------
__global__ void __launch_bounds__(256) raw_kernel(
    const float* __restrict__ x, float* __restrict__ out_raw)
{
    int m    = (blockIdx.x * 256 + threadIdx.x) >> 5;
    int lane = threadIdx.x & 31;
    int b    = m >> 12;
    const float* xr = x + (size_t)m * DM;
    const float* hp = g_hproj + b * DM;
    float acc = 0.f;
    for (int d = lane * 4; d < DM; d += 128) {
        float4 xv = *(const float4*)&xr[d];
        float4 hv = *(const float4*)&hp[d];
        acc += xv.x*hv.x + xv.y*hv.y + xv.z*hv.z + xv.w*hv.w;
    }
#pragma unroll
    for (int o = 16; o > 0; o >>= 1) acc += __shfl_xor_sync(0xffffffffu, acc, o);
    if (lane == 0) { g_raw[m] = acc; out_raw[m] = acc; }
}

// ---------------- softmax over seq ----------------------------------------------
__global__ void __launch_bounds__(1024) softmax_kernel(float* __restrict__ out_imp)
{
    int b   = blockIdx.x;
    int tid = threadIdx.x;
    const float* r = g_raw + (size_t)b * SEQ;
    float4 rv = *(const float4*)&r[tid * 4];
    float v0 = rv.x * 2.0f, v1 = rv.y * 2.0f, v2 = rv.z * 2.0f, v3 = rv.w * 2.0f;
    float mx = fmaxf(fmaxf(v0, v1), fmaxf(v2, v3));

    __shared__ float swarp[32];
    __shared__ float bval;
#pragma unroll
    for (int o = 16; o > 0; o >>= 1) mx = fmaxf(mx, __shfl_xor_sync(0xffffffffu, mx, o));
    if ((tid & 31) == 0) swarp[tid >> 5] = mx;
    __syncthreads();
    if (tid < 32) {
        float v = swarp[tid];
#pragma unroll
        for (int o = 16; o > 0; o >>= 1) v = fmaxf(v, __shfl_xor_sync(0xffffffffu, v, o));
        if (tid == 0) bval = v;
    }
    __syncthreads();
    float gmax = bval;
    float e0 = __expf(v0 - gmax), e1 = __expf(v1 - gmax);
    float e2 = __expf(v2 - gmax), e3 = __expf(v3 - gmax);
    float sum = e0 + e1 + e2 + e3;
#pragma unroll
    for (int o = 16; o > 0; o >>= 1) sum += __shfl_xor_sync(0xffffffffu, sum, o);
    __syncthreads();
    if ((tid & 31) == 0) swarp[tid >> 5] = sum;
    __syncthreads();
    if (tid < 32) {
        float v = swarp[tid];
#pragma unroll
        for (int o = 16; o > 0; o >>= 1) v += __shfl_xor_sync(0xffffffffu, v, o);
        if (tid == 0) bval = v;
    }
    __syncthreads();
    float inv = 1.0f / bval;
    float4 o4; o4.x = e0 * inv; o4.y = e1 * inv; o4.z = e2 * inv; o4.w = e3 * inv;
    *(float4*)&out_imp[(size_t)b * SEQ + tid * 4] = o4;
}

// ---------------- launch ----------------------------------------------------------
extern "C" void kernel_launch(void* const* d_in, const int* in_sizes, int n_in,
                              void* d_out, int out_size)
{
    const float* x       = (const float*)d_in[0];
    const float* A_log   = (const float*)d_in[1];
    const float* W_delta = (const float*)d_in[2];
    const float* W_B     = (const float*)d_in[3];
    const float* W_C     = (const float*)d_in[4];
    const float* gamma   = (const float*)d_in[5];
    const float* beta    = (const float*)d_in[6];
    const float* W_ctx   = (const float*)d_in[7];
    const float* scale   = (const float*)d_in[8];
    const float* W_imp   = (const float*)d_in[9];

    float* out     = (float*)d_out;
    float* out_imp = out;
    float* out_ctx = out + M_ROWS;
    float* out_raw = out + M_ROWS + (size_t)M_ROWS * DM;

    float *p_delta;
    __nv_bfloat16 *p_xbig, *p_sbig, *p_wcomb, *p_wc;
    cudaGetSymbolAddress((void**)&p_delta, g_delta);
    cudaGetSymbolAddress((void**)&p_xbig,  g_xbig);
    cudaGetSymbolAddress((void**)&p_sbig,  g_sbig);
    cudaGetSymbolAddress((void**)&p_wcomb, g_wcomb);
    cudaGetSymbolAddress((void**)&p_wc,    g_wc);

    convert_x  <<<M_ROWS, 256>>>(x);
    convert_wd <<<DM, 256>>>(W_delta);
    convert_wbc<<<KBIG, 128>>>(W_B, W_C);
    convert_wc <<<DM, 256>>>(W_ctx);

    // delta = softplus(x@W_delta), B_sel = x@W_B, C_sel = x@W_C  (one GEMM)
    mma_gemm<1><<<dim3(NB1 / 128, M_ROWS / 128), 256>>>(p_xbig, p_wcomb, p_delta, nullptr, NB1);

    // chunked selective scan
    scan_pass1<<<BATCH * 64 * NCH, 256>>>(x, A_log);
    scan_pass2<<<128, 256>>>(A_log);
    scan_pass3<<<BATCH * 64 * NCH, 256>>>(x, A_log);

    ln_kernel<<<M_ROWS, 256>>>(gamma, beta);

    hproj_kernel<<<dim3(DM / 256, BATCH), 256>>>(W_imp);
    raw_kernel<<<M_ROWS / 8, 256>>>(x, out_raw);
    softmax_kernel<<<BATCH, 1024>>>(out_imp);

    // context = ln(ssm) @ W_ctx * scale
    mma_gemm<0><<<dim3(DM / 128, M_ROWS / 128), 256>>>(p_sbig, p_wc, out_ctx, scale, DM);
}

// round 6
// speedup vs baseline: 2.3572x; 1.0754x over previous
#include <cuda_runtime.h>
#include <cuda_bf16.h>
#include <math.h>
#include <stdint.h>

#define BATCH 2
#define SEQ 4096
#define DM 1024
#define SD 16
#define M_ROWS (BATCH*SEQ)   // 8192
#define NB1 1152             // GEMM1 N (1024 delta + 16 B + 16 C + 96 pad)
#define NCH 16
#define CHL (SEQ/NCH)        // 256

// ---------------- scratch (device globals) -----------------------------------
__device__ float g_delta[(size_t)M_ROWS * DM];
__device__ float g_Bsel [(size_t)M_ROWS * SD];
__device__ float g_Csel [(size_t)M_ROWS * SD];
__device__ float g_ssm  [(size_t)M_ROWS * DM];
__device__ float g_hfinal[BATCH * DM];
__device__ float g_hproj [BATCH * DM];
__device__ float g_raw  [M_ROWS];
__device__ float g_hchunk[(size_t)BATCH * NCH * DM * SD];
__device__ float g_hinit [(size_t)BATCH * NCH * DM * SD];
__device__ float g_sumdel[(size_t)BATCH * NCH * DM];
__device__ __nv_bfloat16 g_xh[(size_t)M_ROWS * DM];      // x hi
__device__ __nv_bfloat16 g_xl[(size_t)M_ROWS * DM];      // x lo
__device__ __nv_bfloat16 g_sh[(size_t)M_ROWS * DM];      // ln(ssm) hi
__device__ __nv_bfloat16 g_sl[(size_t)M_ROWS * DM];      // ln(ssm) lo
__device__ __nv_bfloat16 g_w1[(size_t)2 * DM * NB1];     // [k<1024: hi][k+1024: lo], Wd|WB|WC|0
__device__ __nv_bfloat16 g_w2[(size_t)2 * DM * DM];      // W_ctx hi/lo

// ---------------- PTX helpers ------------------------------------------------
__device__ __forceinline__ void ldsm_x4(uint32_t r[4], uint32_t addr) {
    asm volatile("ldmatrix.sync.aligned.m8n8.x4.shared.b16 {%0,%1,%2,%3}, [%4];\n"
        : "=r"(r[0]), "=r"(r[1]), "=r"(r[2]), "=r"(r[3]) : "r"(addr));
}
__device__ __forceinline__ void ldsm_x4_t(uint32_t r[4], uint32_t addr) {
    asm volatile("ldmatrix.sync.aligned.m8n8.x4.trans.shared.b16 {%0,%1,%2,%3}, [%4];\n"
        : "=r"(r[0]), "=r"(r[1]), "=r"(r[2]), "=r"(r[3]) : "r"(addr));
}
__device__ __forceinline__ void mma_bf16(float c[4], const uint32_t a[4],
                                         uint32_t b0, uint32_t b1) {
    asm volatile("mma.sync.aligned.m16n8k16.row.col.f32.bf16.bf16.f32 "
        "{%0,%1,%2,%3}, {%4,%5,%6,%7}, {%8,%9}, {%0,%1,%2,%3};\n"
        : "+f"(c[0]), "+f"(c[1]), "+f"(c[2]), "+f"(c[3])
        : "r"(a[0]), "r"(a[1]), "r"(a[2]), "r"(a[3]), "r"(b0), "r"(b1));
}
__device__ __forceinline__ void cp16(uint32_t saddr, const void* gaddr) {
    asm volatile("cp.async.cg.shared.global [%0], [%1], 16;\n" :: "r"(saddr), "l"(gaddr));
}

// ---------------- smem layout for GEMM (dynamic) -------------------------------
// Ah[2][128][40], Al[2][128][40], Bh[2][32][136], Bl[2][32][136]  (bf16)
#define ASTG 10240          // bytes per A stage (128*40*2)
#define BSTG 8704           // bytes per B stage (32*136*2)
#define ASH_OFF 0
#define ASL_OFF (2*ASTG)            // 20480
#define BSH_OFF (4*ASTG)            // 40960
#define BSL_OFF (4*ASTG + 2*BSTG)   // 58368
#define GSMEM   (4*ASTG + 4*BSTG)   // 75776

// ---------------- dual-split bf16 HMMA GEMM ------------------------------------
// C[M x N] = (Ah+Al)[M x 1024] @ (Bh+Bl)[1024 x N] via AhBh + AhBl + AlBh.
// Block 128x128, BK=32, 8 warps (2x4), warp tile 64x32.
// MODE 0: out = acc*scale -> C (stride DM). MODE 1: col<1024 softplus->g_delta,
// [1024,1040)->g_Bsel, [1040,1056)->g_Csel, rest dropped.
template<int MODE>
__global__ void __launch_bounds__(256, 2) hmma_gemm(
    const __nv_bfloat16* __restrict__ Ahg, const __nv_bfloat16* __restrict__ Alg,
    const __nv_bfloat16* __restrict__ Bhg, const __nv_bfloat16* __restrict__ Blg,
    float* __restrict__ C, const float* __restrict__ scale_ptr, int N)
{
    extern __shared__ char smem[];
    uint32_t sb = (uint32_t)__cvta_generic_to_shared(smem);

    const int tid  = threadIdx.x;
    const int warp = tid >> 5, lane = tid & 31;
    const int wm = warp >> 2, wn = warp & 3;
    const int brow = blockIdx.y * 128, bcol = blockIdx.x * 128;

    float acc[4][4][4];
#pragma unroll
    for (int i = 0; i < 4; i++)
#pragma unroll
        for (int j = 0; j < 4; j++)
#pragma unroll
            for (int c = 0; c < 4; c++) acc[i][j][c] = 0.f;

    const __nv_bfloat16* Ah = Ahg + (size_t)brow * DM;
    const __nv_bfloat16* Al = Alg + (size_t)brow * DM;
    const __nv_bfloat16* Bh = Bhg + bcol;
    const __nv_bfloat16* Bl = Blg + bcol;

    auto load_stage = [&](int s, int k0) {
#pragma unroll
        for (int i = 0; i < 2; i++) {              // A tiles: 128 x 32
            int idx = tid + i * 256;               // 0..511
            int r = idx >> 2, c = (idx & 3) * 8;
            uint32_t so = (uint32_t)((r * 40 + c) * 2);
            const size_t go = (size_t)r * DM + k0 + c;
            cp16(sb + ASH_OFF + s * ASTG + so, Ah + go);
            cp16(sb + ASL_OFF + s * ASTG + so, Al + go);
        }
#pragma unroll
        for (int i = 0; i < 2; i++) {              // B tiles: 32 x 128
            int idx = tid + i * 256;
            int r = idx >> 4, c = (idx & 15) * 8;
            uint32_t so = (uint32_t)((r * 136 + c) * 2);
            const size_t go = (size_t)(k0 + r) * N + c;
            cp16(sb + BSH_OFF + s * BSTG + so, Bh + go);
            cp16(sb + BSL_OFF + s * BSTG + so, Bl + go);
        }
        asm volatile("cp.async.commit_group;\n");
    };

    load_stage(0, 0);
    asm volatile("cp.async.wait_group 0;\n");
    __syncthreads();

    const int NK = DM / 32;   // 32 chunks
    for (int kt = 0; kt < NK; kt++) {
        int cur = kt & 1;
        if (kt + 1 < NK) load_stage(cur ^ 1, (kt + 1) * 32);

#pragma unroll
        for (int kk = 0; kk < 32; kk += 16) {
            // A row / B row-col indices for ldmatrix
            uint32_t a_off = (uint32_t)(((wm * 64 + (lane & 15)) * 40 + kk + (lane >> 4) * 8) * 2);
            uint32_t b_off0 = (uint32_t)(((kk + (lane & 15)) * 136 + wn * 32 + (lane >> 4) * 8) * 2);
            uint32_t b_off1 = b_off0 + 16 * 2;

            uint32_t ah[4][4];
#pragma unroll
            for (int mt = 0; mt < 4; mt++)
                ldsm_x4(ah[mt], sb + ASH_OFF + cur * ASTG + a_off + (uint32_t)(mt * 16 * 40 * 2));

            uint32_t bh_[2][4];
            ldsm_x4_t(bh_[0], sb + BSH_OFF + cur * BSTG + b_off0);
            ldsm_x4_t(bh_[1], sb + BSH_OFF + cur * BSTG + b_off1);
#pragma unroll
            for (int mt = 0; mt < 4; mt++)
#pragma unroll
                for (int nt = 0; nt < 4; nt++)
                    mma_bf16(acc[mt][nt], ah[mt],
                             bh_[nt >> 1][(nt & 1) * 2], bh_[nt >> 1][(nt & 1) * 2 + 1]);

            {   // Ah x Bl  (reuse ah)
                uint32_t bl_[2][4];
                ldsm_x4_t(bl_[0], sb + BSL_OFF + cur * BSTG + b_off0);
                ldsm_x4_t(bl_[1], sb + BSL_OFF + cur * BSTG + b_off1);
#pragma unroll
                for (int mt = 0; mt < 4; mt++)
#pragma unroll
                    for (int nt = 0; nt < 4; nt++)
                        mma_bf16(acc[mt][nt], ah[mt],
                                 bl_[nt >> 1][(nt & 1) * 2], bl_[nt >> 1][(nt & 1) * 2 + 1]);
            }
            {   // Al x Bh  (reuse bh_)
                uint32_t al[4][4];
#pragma unroll
                for (int mt = 0; mt < 4; mt++)
                    ldsm_x4(al[mt], sb + ASL_OFF + cur * ASTG + a_off + (uint32_t)(mt * 16 * 40 * 2));
#pragma unroll
                for (int mt = 0; mt < 4; mt++)
#pragma unroll
                    for (int nt = 0; nt < 4; nt++)
                        mma_bf16(acc[mt][nt], al[mt],
                                 bh_[nt >> 1][(nt & 1) * 2], bh_[nt >> 1][(nt & 1) * 2 + 1]);
            }
        }
        if (kt + 1 < NK) asm volatile("cp.async.wait_group 0;\n");
        __syncthreads();
    }

    float scl = 1.0f;
    if (MODE == 0 && scale_ptr) scl = *scale_ptr;
    const int g = lane >> 2, tg = lane & 3;
#pragma unroll
    for (int mt = 0; mt < 4; mt++) {
#pragma unroll
        for (int nt = 0; nt < 4; nt++) {
            int col = bcol + wn * 32 + nt * 8 + tg * 2;
#pragma unroll
            for (int half = 0; half < 2; half++) {
                int row = brow + wm * 64 + mt * 16 + g + half * 8;
                float v0 = acc[mt][nt][half * 2], v1 = acc[mt][nt][half * 2 + 1];
                if (MODE == 0) {
                    *(float2*)&C[(size_t)row * DM + col] = make_float2(v0 * scl, v1 * scl);
                } else {
                    if (col < DM) {
                        v0 = fmaxf(v0, 0.f) + log1pf(__expf(-fabsf(v0)));
                        v1 = fmaxf(v1, 0.f) + log1pf(__expf(-fabsf(v1)));
                        *(float2*)&g_delta[(size_t)row * DM + col] = make_float2(v0, v1);
                    } else if (col < DM + SD) {
                        *(float2*)&g_Bsel[(size_t)row * SD + col - DM] = make_float2(v0, v1);
                    } else if (col < DM + 2 * SD) {
                        *(float2*)&g_Csel[(size_t)row * SD + col - DM - SD] = make_float2(v0, v1);
                    }
                }
            }
        }
    }
}

// ---------------- fp32 -> bf16 hi/lo split --------------------------------------
__device__ __forceinline__ void split4(float4 v, uint2& hp, uint2& lp) {
    __nv_bfloat162 h01 = __floats2bfloat162_rn(v.x, v.y);
    __nv_bfloat162 h23 = __floats2bfloat162_rn(v.z, v.w);
    float lx = v.x - __bfloat162float(h01.x);
    float ly = v.y - __bfloat162float(h01.y);
    float lz = v.z - __bfloat162float(h23.x);
    float lw = v.w - __bfloat162float(h23.y);
    __nv_bfloat162 l01 = __floats2bfloat162_rn(lx, ly);
    __nv_bfloat162 l23 = __floats2bfloat162_rn(lz, lw);
    hp.x = *(uint32_t*)&h01; hp.y = *(uint32_t*)&h23;
    lp.x = *(uint32_t*)&l01; lp.y = *(uint32_t*)&l23;
}

__global__ void __launch_bounds__(256) convert_x(const float* __restrict__ x)
{
    int m = blockIdx.x, j = threadIdx.x * 4;
    float4 v = *(const float4*)&x[(size_t)m * DM + j];
    uint2 hp, lp; split4(v, hp, lp);
    *(uint2*)&g_xh[(size_t)m * DM + j] = hp;
    *(uint2*)&g_xl[(size_t)m * DM + j] = lp;
}

// W_delta -> g_w1 cols [0,1024): row k hi, row k+1024 lo
__global__ void __launch_bounds__(256) convert_wd(const float* __restrict__ W)
{
    int k = blockIdx.x, j = threadIdx.x * 4;
    float4 v = *(const float4*)&W[(size_t)k * DM + j];
    uint2 hp, lp; split4(v, hp, lp);
    *(uint2*)&g_w1[(size_t)k * NB1 + j]        = hp;
    *(uint2*)&g_w1[(size_t)(k + DM) * NB1 + j] = lp;
}

// W_B / W_C -> g_w1 cols [1024,1152)
__global__ void __launch_bounds__(128) convert_wbc(
    const float* __restrict__ WB, const float* __restrict__ WC)
{
    int k = blockIdx.x, t = threadIdx.x;   // t 0..127
    float v = 0.f;
    if (t < SD) v = WB[k * SD + t];
    else if (t < 2 * SD) v = WC[k * SD + t - SD];
    __nv_bfloat16 h = __float2bfloat16(v);
    __nv_bfloat16 l = __float2bfloat16(v - __bfloat162float(h));
    g_w1[(size_t)k * NB1 + DM + t]        = h;
    g_w1[(size_t)(k + DM) * NB1 + DM + t] = l;
}

// W_ctx -> g_w2
__global__ void __launch_bounds__(256) convert_wc(const float* __restrict__ W)
{
    int k = blockIdx.x, j = threadIdx.x * 4;
    float4 v = *(const float4*)&W[(size_t)k * DM + j];
    uint2 hp, lp; split4(v, hp, lp);
    *(uint2*)&g_w2[(size_t)k * DM + j]        = hp;
    *(uint2*)&g_w2[(size_t)(k + DM) * DM + j] = lp;
}

// ---------------- chunked selective scan ------------------------------------------
#define TC 128
__global__ void __launch_bounds__(256) scan_pass1(
    const float* __restrict__ x, const float* __restrict__ A_log)
{
    int blk  = blockIdx.x;
    int c    = blk & (NCH - 1);
    int dblk = (blk >> 4) & 63;
    int b    = blk >> 10;
    int tid  = threadIdx.x;
    int g    = tid >> 4, n = tid & 15;
    int d0   = dblk << 4, d = d0 + g;

    __shared__ float s_delta[TC][16];
    __shared__ float s_x    [TC][16];
    __shared__ float s_B    [TC][16];

    float a = -__expf(A_log[d * SD + n]);
    float h = 0.f, sdt = 0.f;

    const float* dbase = g_delta + ((size_t)b * SEQ) * DM + d0;
    const float* xbase = x       + ((size_t)b * SEQ) * DM + d0;
    const float* Bbase = g_Bsel  + ((size_t)b * SEQ) * SD;
    int lr = tid >> 4, lc = tid & 15;
    int tstart = c * CHL;

    for (int t0 = tstart; t0 < tstart + CHL; t0 += TC) {
        __syncthreads();
        for (int r = lr; r < TC; r += 16) {
            s_delta[r][lc] = dbase[(size_t)(t0 + r) * DM + lc];
            s_x[r][lc]     = xbase[(size_t)(t0 + r) * DM + lc];
            s_B[r][lc]     = Bbase[(size_t)(t0 + r) * SD + lc];
        }
        __syncthreads();
#pragma unroll 8
        for (int t = 0; t < TC; t++) {
            float dt = s_delta[t][g];
            float xv = s_x[t][g];
            float bn = s_B[t][n];
            h = fmaf(h, __expf(dt * a), dt * xv * bn);
            sdt += dt;
        }
    }
    size_t ci = ((size_t)(b * NCH + c) * DM + d) * SD + n;
    g_hchunk[ci] = h;
    if (n == 0) g_sumdel[(size_t)(b * NCH + c) * DM + d] = sdt;
}

__global__ void __launch_bounds__(256) scan_pass2(const float* __restrict__ A_log)
{
    int idx = blockIdx.x * 256 + threadIdx.x;
    int n = idx & 15, d = (idx >> 4) & (DM - 1), b = idx >> 14;
    float a = -__expf(A_log[d * SD + n]);
    float H = 0.f;
#pragma unroll
    for (int c = 0; c < NCH; c++) {
        size_t ci = ((size_t)(b * NCH + c) * DM + d) * SD + n;
        g_hinit[ci] = H;
        float S = g_sumdel[(size_t)(b * NCH + c) * DM + d];
        H = __expf(a * S) * H + g_hchunk[ci];
    }
}

__global__ void __launch_bounds__(256) scan_pass3(
    const float* __restrict__ x, const float* __restrict__ A_log)
{
    int blk  = blockIdx.x;
    int c    = blk & (NCH - 1);
    int dblk = (blk >> 4) & 63;
    int b    = blk >> 10;
    int tid  = threadIdx.x;
    int g    = tid >> 4, n = tid & 15;
    int d0   = dblk << 4, d = d0 + g;

    __shared__ float s_delta[TC][16];
    __shared__ float s_x    [TC][16];
    __shared__ float s_B    [TC][16];
    __shared__ float s_C    [TC][16];
    __shared__ float s_y    [TC][16];

    float a = -__expf(A_log[d * SD + n]);
    float h = g_hinit[((size_t)(b * NCH + c) * DM + d) * SD + n];

    const float* dbase = g_delta + ((size_t)b * SEQ) * DM + d0;
    const float* xbase = x       + ((size_t)b * SEQ) * DM + d0;
    const float* Bbase = g_Bsel  + ((size_t)b * SEQ) * SD;
    const float* Cbase = g_Csel  + ((size_t)b * SEQ) * SD;
    float*       ybase = g_ssm   + ((size_t)b * SEQ) * DM + d0;
    int lr = tid >> 4, lc = tid & 15;
    int tstart = c * CHL;

    for (int t0 = tstart; t0 < tstart + CHL; t0 += TC) {
        __syncthreads();
        for (int r = lr; r < TC; r += 16) {
            s_delta[r][lc] = dbase[(size_t)(t0 + r) * DM + lc];
            s_x[r][lc]     = xbase[(size_t)(t0 + r) * DM + lc];
            s_B[r][lc]     = Bbase[(size_t)(t0 + r) * SD + lc];
            s_C[r][lc]     = Cbase[(size_t)(t0 + r) * SD + lc];
        }
        __syncthreads();
#pragma unroll 4
        for (int t = 0; t < TC; t++) {
            float dt = s_delta[t][g];
            float xv = s_x[t][g];
            float bn = s_B[t][n];
            float cn = s_C[t][n];
            h = fmaf(h, __expf(dt * a), dt * xv * bn);
            float p = h * cn;
            p += __shfl_xor_sync(0xffffffffu, p, 8);
            p += __shfl_xor_sync(0xffffffffu, p, 4);
            p += __shfl_xor_sync(0xffffffffu, p, 2);
            p += __shfl_xor_sync(0xffffffffu, p, 1);
            if (n == 0) s_y[t][g] = p;
        }
        __syncthreads();
        for (int r = lr; r < TC; r += 16)
            ybase[(size_t)(t0 + r) * DM + lc] = s_y[r][lc];
    }
}

// ---------------- layernorm -> bf16 splits + h_final ------------------------------
__global__ void __launch_bounds__(256) ln_kernel(
    const float* __restrict__ gamma, const float* __restrict__ beta)
{
    int m = blockIdx.x;
    const float* row = g_ssm + (size_t)m * DM;
    int tid = threadIdx.x;
    float4 v = *(const float4*)&row[tid * 4];
    float s  = v.x + v.y + v.z + v.w;
    float ss = v.x*v.x + v.y*v.y + v.z*v.z + v.w*v.w;
#pragma unroll
    for (int o = 16; o > 0; o >>= 1) {
        s  += __shfl_xor_sync(0xffffffffu, s,  o);
        ss += __shfl_xor_sync(0xffffffffu, ss, o);
    }
    __shared__ float rs[8], rss[8];
    if ((tid & 31) == 0) { rs[tid >> 5] = s; rss[tid >> 5] = ss; }
    __syncthreads();
    s = 0.f; ss = 0.f;
#pragma unroll
    for (int i = 0; i < 8; i++) { s += rs[i]; ss += rss[i]; }
    float mu  = s * (1.0f / DM);
    float var = ss * (1.0f / DM) - mu * mu;
    float inv = rsqrtf(var + 1e-5f);
    float4 g4 = *(const float4*)&gamma[tid * 4];
    float4 b4 = *(const float4*)&beta[tid * 4];
    v.x = (v.x - mu) * inv * g4.x + b4.x;
    v.y = (v.y - mu) * inv * g4.y + b4.y;
    v.z = (v.z - mu) * inv * g4.z + b4.z;
    v.w = (v.w - mu) * inv * g4.w + b4.w;

    uint2 hp, lp; split4(v, hp, lp);
    *(uint2*)&g_sh[(size_t)m * DM + tid * 4] = hp;
    *(uint2*)&g_sl[(size_t)m * DM + tid * 4] = lp;

    if ((m & (SEQ - 1)) == SEQ - 1) {
        int b = m / SEQ;
        *(float4*)&g_hfinal[b * DM + tid * 4] = v;
    }
}

// ---------------- h_proj = h_final @ W_imp -----------------------------------------
__global__ void __launch_bounds__(256) hproj_kernel(const float* __restrict__ Wimp)
{
    int b = blockIdx.y;
    int j = blockIdx.x * 256 + threadIdx.x;
    __shared__ float hf[DM];
    for (int i = threadIdx.x; i < DM; i += 256) hf[i] = g_hfinal[b * DM + i];
    __syncthreads();
    float acc = 0.f;
#pragma unroll 8
    for (int d = 0; d < DM; d++)
        acc = fmaf(hf[d], Wimp[(size_t)d * DM + j], acc);
    g_hproj[b * DM + j] = acc;
}

// ---------------- raw_importance -----------------------------------------------------
__global__ void __launch_bounds__(256) raw_kernel(
    const float* __restrict__ x, float* __restrict__ out_raw)
{
    int m    = (blockIdx.x * 256 + threadIdx.x) >> 5;
    int lane = threadIdx.x & 31;
    int b    = m >> 12;
    const float* xr = x + (size_t)m * DM;
    const float* hp = g_hproj + b * DM;
    float acc = 0.f;
    for (int d = lane * 4; d < DM; d += 128) {
        float4 xv = *(const float4*)&xr[d];
        float4 hv = *(const float4*)&hp[d];
        acc += xv.x*hv.x + xv.y*hv.y + xv.z*hv.z + xv.w*hv.w;
    }
#pragma unroll
    for (int o = 16; o > 0; o >>= 1) acc += __shfl_xor_sync(0xffffffffu, acc, o);
    if (lane == 0) { g_raw[m] = acc; out_raw[m] = acc; }
}

// ---------------- softmax over seq ---------------------------------------------------
__global__ void __launch_bounds__(1024) softmax_kernel(float* __restrict__ out_imp)
{
    int b   = blockIdx.x;
    int tid = threadIdx.x;
    const float* r = g_raw + (size_t)b * SEQ;
    float4 rv = *(const float4*)&r[tid * 4];
    float v0 = rv.x * 2.0f, v1 = rv.y * 2.0f, v2 = rv.z * 2.0f, v3 = rv.w * 2.0f;
    float mx = fmaxf(fmaxf(v0, v1), fmaxf(v2, v3));

    __shared__ float swarp[32];
    __shared__ float bval;
#pragma unroll
    for (int o = 16; o > 0; o >>= 1) mx = fmaxf(mx, __shfl_xor_sync(0xffffffffu, mx, o));
    if ((tid & 31) == 0) swarp[tid >> 5] = mx;
    __syncthreads();
    if (tid < 32) {
        float v = swarp[tid];
#pragma unroll
        for (int o = 16; o > 0; o >>= 1) v = fmaxf(v, __shfl_xor_sync(0xffffffffu, v, o));
        if (tid == 0) bval = v;
    }
    __syncthreads();
    float gmax = bval;
    float e0 = __expf(v0 - gmax), e1 = __expf(v1 - gmax);
    float e2 = __expf(v2 - gmax), e3 = __expf(v3 - gmax);
    float sum = e0 + e1 + e2 + e3;
#pragma unroll
    for (int o = 16; o > 0; o >>= 1) sum += __shfl_xor_sync(0xffffffffu, sum, o);
    __syncthreads();
    if ((tid & 31) == 0) swarp[tid >> 5] = sum;
    __syncthreads();
    if (tid < 32) {
        float v = swarp[tid];
#pragma unroll
        for (int o = 16; o > 0; o >>= 1) v += __shfl_xor_sync(0xffffffffu, v, o);
        if (tid == 0) bval = v;
    }
    __syncthreads();
    float inv = 1.0f / bval;
    float4 o4; o4.x = e0 * inv; o4.y = e1 * inv; o4.z = e2 * inv; o4.w = e3 * inv;
    *(float4*)&out_imp[(size_t)b * SEQ + tid * 4] = o4;
}

// ---------------- launch ---------------------------------------------------------------
extern "C" void kernel_launch(void* const* d_in, const int* in_sizes, int n_in,
                              void* d_out, int out_size)
{
    const float* x       = (const float*)d_in[0];
    const float* A_log   = (const float*)d_in[1];
    const float* W_delta = (const float*)d_in[2];
    const float* W_B     = (const float*)d_in[3];
    const float* W_C     = (const float*)d_in[4];
    const float* gamma   = (const float*)d_in[5];
    const float* beta    = (const float*)d_in[6];
    const float* W_ctx   = (const float*)d_in[7];
    const float* scale   = (const float*)d_in[8];
    const float* W_imp   = (const float*)d_in[9];

    float* out     = (float*)d_out;
    float* out_imp = out;
    float* out_ctx = out + M_ROWS;
    float* out_raw = out + M_ROWS + (size_t)M_ROWS * DM;

    __nv_bfloat16 *p_xh, *p_xl, *p_sh, *p_sl, *p_w1, *p_w2;
    cudaGetSymbolAddress((void**)&p_xh, g_xh);
    cudaGetSymbolAddress((void**)&p_xl, g_xl);
    cudaGetSymbolAddress((void**)&p_sh, g_sh);
    cudaGetSymbolAddress((void**)&p_sl, g_sl);
    cudaGetSymbolAddress((void**)&p_w1, g_w1);
    cudaGetSymbolAddress((void**)&p_w2, g_w2);

    cudaFuncSetAttribute(hmma_gemm<0>, cudaFuncAttributeMaxDynamicSharedMemorySize, GSMEM);
    cudaFuncSetAttribute(hmma_gemm<1>, cudaFuncAttributeMaxDynamicSharedMemorySize, GSMEM);

    convert_x  <<<M_ROWS, 256>>>(x);
    convert_wd <<<DM, 256>>>(W_delta);
    convert_wbc<<<DM, 128>>>(W_B, W_C);
    convert_wc <<<DM, 256>>>(W_ctx);

    // GEMM1: delta (softplus) + B_sel + C_sel
    hmma_gemm<1><<<dim3(NB1 / 128, M_ROWS / 128), 256, GSMEM>>>(
        p_xh, p_xl, p_w1, p_w1 + (size_t)DM * NB1, nullptr, nullptr, NB1);

    scan_pass1<<<BATCH * 64 * NCH, 256>>>(x, A_log);
    scan_pass2<<<128, 256>>>(A_log);
    scan_pass3<<<BATCH * 64 * NCH, 256>>>(x, A_log);

    ln_kernel<<<M_ROWS, 256>>>(gamma, beta);

    hproj_kernel<<<dim3(DM / 256, BATCH), 256>>>(W_imp);
    raw_kernel<<<M_ROWS / 8, 256>>>(x, out_raw);
    softmax_kernel<<<BATCH, 1024>>>(out_imp);

    // GEMM2: context = ln(ssm) @ W_ctx * scale
    hmma_gemm<0><<<dim3(DM / 128, M_ROWS / 128), 256, GSMEM>>>(
        p_sh, p_sl, p_w2, p_w2 + (size_t)DM * DM, out_ctx, scale, DM);
}

// round 7
// speedup vs baseline: 2.3791x; 1.0093x over previous
#include <cuda_runtime.h>
#include <cuda_bf16.h>
#include <math.h>
#include <stdint.h>

#define BATCH 2
#define SEQ 4096
#define DM 1024
#define SD 16
#define M_ROWS (BATCH*SEQ)   // 8192
#define NB1 1152             // GEMM1 N (1024 delta + 16 B + 16 C + 96 pad)
#define NCH 16
#define CHL (SEQ/NCH)        // 256
#define LOG2E 1.4426950408889634f

// ---------------- scratch (device globals) -----------------------------------
__device__ float g_delta[(size_t)M_ROWS * DM];
__device__ float g_Bsel [(size_t)M_ROWS * SD];
__device__ float g_Csel [(size_t)M_ROWS * SD];
__device__ float g_ssm  [(size_t)M_ROWS * DM];
__device__ float g_hfinal[BATCH * DM];
__device__ float g_hproj [BATCH * DM];
__device__ float g_raw  [M_ROWS];
__device__ float g_hchunk[(size_t)BATCH * NCH * DM * SD];
__device__ float g_hinit [(size_t)BATCH * NCH * DM * SD];
__device__ float g_sumdel[(size_t)BATCH * NCH * DM];
__device__ __nv_bfloat16 g_xh[(size_t)M_ROWS * DM];
__device__ __nv_bfloat16 g_xl[(size_t)M_ROWS * DM];
__device__ __nv_bfloat16 g_sh[(size_t)M_ROWS * DM];
__device__ __nv_bfloat16 g_sl[(size_t)M_ROWS * DM];
__device__ __nv_bfloat16 g_w1[(size_t)2 * DM * NB1];     // [k<1024 hi][k+1024 lo]
__device__ __nv_bfloat16 g_w2[(size_t)2 * DM * DM];      // W_ctx hi/lo

// ---------------- PTX helpers ------------------------------------------------
__device__ __forceinline__ void ldsm_x4(uint32_t r[4], uint32_t addr) {
    asm volatile("ldmatrix.sync.aligned.m8n8.x4.shared.b16 {%0,%1,%2,%3}, [%4];\n"
        : "=r"(r[0]), "=r"(r[1]), "=r"(r[2]), "=r"(r[3]) : "r"(addr));
}
__device__ __forceinline__ void ldsm_x4_t(uint32_t r[4], uint32_t addr) {
    asm volatile("ldmatrix.sync.aligned.m8n8.x4.trans.shared.b16 {%0,%1,%2,%3}, [%4];\n"
        : "=r"(r[0]), "=r"(r[1]), "=r"(r[2]), "=r"(r[3]) : "r"(addr));
}
__device__ __forceinline__ void mma_bf16(float c[4], const uint32_t a[4],
                                         uint32_t b0, uint32_t b1) {
    asm volatile("mma.sync.aligned.m16n8k16.row.col.f32.bf16.bf16.f32 "
        "{%0,%1,%2,%3}, {%4,%5,%6,%7}, {%8,%9}, {%0,%1,%2,%3};\n"
        : "+f"(c[0]), "+f"(c[1]), "+f"(c[2]), "+f"(c[3])
        : "r"(a[0]), "r"(a[1]), "r"(a[2]), "r"(a[3]), "r"(b0), "r"(b1));
}
__device__ __forceinline__ void cp16(uint32_t saddr, const void* gaddr) {
    asm volatile("cp.async.cg.shared.global [%0], [%1], 16;\n" :: "r"(saddr), "l"(gaddr));
}

// ---------------- GEMM smem layout (3-stage) -----------------------------------
#define ASTG 10240                   // 128*40*2
#define BSTG 8704                    // 32*136*2
#define STGB (2*ASTG + 2*BSTG)       // 37888 per stage
#define GSMEM (3*STGB)               // 113664
// within stage: Ah @0, Al @ASTG, Bh @2*ASTG, Bl @2*ASTG+BSTG

// ---------------- dual-split bf16 HMMA GEMM ------------------------------------
template<int MODE>
__global__ void __launch_bounds__(256, 2) hmma_gemm(
    const __nv_bfloat16* __restrict__ Ahg, const __nv_bfloat16* __restrict__ Alg,
    const __nv_bfloat16* __restrict__ Bhg, const __nv_bfloat16* __restrict__ Blg,
    float* __restrict__ C, const float* __restrict__ scale_ptr, int N)
{
    extern __shared__ char smem[];
    uint32_t sb = (uint32_t)__cvta_generic_to_shared(smem);

    const int tid  = threadIdx.x;
    const int warp = tid >> 5, lane = tid & 31;
    const int wm = warp >> 2, wn = warp & 3;
    const int brow = blockIdx.y * 128, bcol = blockIdx.x * 128;

    float acc[4][4][4];
#pragma unroll
    for (int i = 0; i < 4; i++)
#pragma unroll
        for (int j = 0; j < 4; j++)
#pragma unroll
            for (int c = 0; c < 4; c++) acc[i][j][c] = 0.f;

    const __nv_bfloat16* Ah = Ahg + (size_t)brow * DM;
    const __nv_bfloat16* Al = Alg + (size_t)brow * DM;
    const __nv_bfloat16* Bh = Bhg + bcol;
    const __nv_bfloat16* Bl = Blg + bcol;

    auto load_stage = [&](int s, int k0) {
        uint32_t base = sb + (uint32_t)(s * STGB);
#pragma unroll
        for (int i = 0; i < 2; i++) {              // A tiles: 128 x 32
            int idx = tid + i * 256;
            int r = idx >> 2, c = (idx & 3) * 8;
            uint32_t so = (uint32_t)((r * 40 + c) * 2);
            const size_t go = (size_t)r * DM + k0 + c;
            cp16(base + so,        Ah + go);
            cp16(base + ASTG + so, Al + go);
        }
#pragma unroll
        for (int i = 0; i < 2; i++) {              // B tiles: 32 x 128
            int idx = tid + i * 256;
            int r = idx >> 4, c = (idx & 15) * 8;
            uint32_t so = (uint32_t)((r * 136 + c) * 2);
            const size_t go = (size_t)(k0 + r) * N + c;
            cp16(base + 2 * ASTG + so,        Bh + go);
            cp16(base + 2 * ASTG + BSTG + so, Bl + go);
        }
    };

    // prologue: 2 stages in flight
    load_stage(0, 0);
    asm volatile("cp.async.commit_group;\n");
    load_stage(1, 32);
    asm volatile("cp.async.commit_group;\n");

    const int NK = DM / 32;   // 32
    int s = 0;
    for (int kt = 0; kt < NK; kt++) {
        asm volatile("cp.async.wait_group 1;\n");   // stage s landed
        __syncthreads();
        // issue loads for kt+2 into the buffer freed last iteration
        if (kt + 2 < NK) {
            int s2 = s + 2; if (s2 >= 3) s2 -= 3;
            load_stage(s2, (kt + 2) * 32);
        }
        asm volatile("cp.async.commit_group;\n");

        uint32_t base = sb + (uint32_t)(s * STGB);
#pragma unroll
        for (int kk = 0; kk < 32; kk += 16) {
            uint32_t a_off = (uint32_t)(((wm * 64 + (lane & 15)) * 40 + kk + (lane >> 4) * 8) * 2);
            uint32_t b_off0 = (uint32_t)(((kk + (lane & 15)) * 136 + wn * 32 + (lane >> 4) * 8) * 2);
            uint32_t b_off1 = b_off0 + 32;

            uint32_t ah[4][4];
#pragma unroll
            for (int mt = 0; mt < 4; mt++)
                ldsm_x4(ah[mt], base + a_off + (uint32_t)(mt * 1280));

            uint32_t bh_[2][4];
            ldsm_x4_t(bh_[0], base + 2 * ASTG + b_off0);
            ldsm_x4_t(bh_[1], base + 2 * ASTG + b_off1);
#pragma unroll
            for (int mt = 0; mt < 4; mt++)
#pragma unroll
                for (int nt = 0; nt < 4; nt++)
                    mma_bf16(acc[mt][nt], ah[mt],
                             bh_[nt >> 1][(nt & 1) * 2], bh_[nt >> 1][(nt & 1) * 2 + 1]);

            {   // Ah x Bl
                uint32_t bl_[2][4];
                ldsm_x4_t(bl_[0], base + 2 * ASTG + BSTG + b_off0);
                ldsm_x4_t(bl_[1], base + 2 * ASTG + BSTG + b_off1);
#pragma unroll
                for (int mt = 0; mt < 4; mt++)
#pragma unroll
                    for (int nt = 0; nt < 4; nt++)
                        mma_bf16(acc[mt][nt], ah[mt],
                                 bl_[nt >> 1][(nt & 1) * 2], bl_[nt >> 1][(nt & 1) * 2 + 1]);
            }
            {   // Al x Bh
                uint32_t al[4][4];
#pragma unroll
                for (int mt = 0; mt < 4; mt++)
                    ldsm_x4(al[mt], base + ASTG + a_off + (uint32_t)(mt * 1280));
#pragma unroll
                for (int mt = 0; mt < 4; mt++)
#pragma unroll
                    for (int nt = 0; nt < 4; nt++)
                        mma_bf16(acc[mt][nt], al[mt],
                                 bh_[nt >> 1][(nt & 1) * 2], bh_[nt >> 1][(nt & 1) * 2 + 1]);
            }
        }
        if (++s >= 3) s -= 3;
    }

    float scl = 1.0f;
    if (MODE == 0 && scale_ptr) scl = *scale_ptr;
    const int g = lane >> 2, tg = lane & 3;
#pragma unroll
    for (int mt = 0; mt < 4; mt++) {
#pragma unroll
        for (int nt = 0; nt < 4; nt++) {
            int col = bcol + wn * 32 + nt * 8 + tg * 2;
#pragma unroll
            for (int half = 0; half < 2; half++) {
                int row = brow + wm * 64 + mt * 16 + g + half * 8;
                float v0 = acc[mt][nt][half * 2], v1 = acc[mt][nt][half * 2 + 1];
                if (MODE == 0) {
                    *(float2*)&C[(size_t)row * DM + col] = make_float2(v0 * scl, v1 * scl);
                } else {
                    if (col < DM) {
                        v0 = fmaxf(v0, 0.f) + log1pf(__expf(-fabsf(v0)));
                        v1 = fmaxf(v1, 0.f) + log1pf(__expf(-fabsf(v1)));
                        *(float2*)&g_delta[(size_t)row * DM + col] = make_float2(v0, v1);
                    } else if (col < DM + SD) {
                        *(float2*)&g_Bsel[(size_t)row * SD + col - DM] = make_float2(v0, v1);
                    } else if (col < DM + 2 * SD) {
                        *(float2*)&g_Csel[(size_t)row * SD + col - DM - SD] = make_float2(v0, v1);
                    }
                }
            }
        }
    }
}

// ---------------- fp32 -> bf16 hi/lo split --------------------------------------
__device__ __forceinline__ void split4(float4 v, uint2& hp, uint2& lp) {
    __nv_bfloat162 h01 = __floats2bfloat162_rn(v.x, v.y);
    __nv_bfloat162 h23 = __floats2bfloat162_rn(v.z, v.w);
    float lx = v.x - __bfloat162float(h01.x);
    float ly = v.y - __bfloat162float(h01.y);
    float lz = v.z - __bfloat162float(h23.x);
    float lw = v.w - __bfloat162float(h23.y);
    __nv_bfloat162 l01 = __floats2bfloat162_rn(lx, ly);
    __nv_bfloat162 l23 = __floats2bfloat162_rn(lz, lw);
    hp.x = *(uint32_t*)&h01; hp.y = *(uint32_t*)&h23;
    lp.x = *(uint32_t*)&l01; lp.y = *(uint32_t*)&l23;
}

__global__ void __launch_bounds__(256) convert_x(const float* __restrict__ x)
{
    int m = blockIdx.x, j = threadIdx.x * 4;
    float4 v = *(const float4*)&x[(size_t)m * DM + j];
    uint2 hp, lp; split4(v, hp, lp);
    *(uint2*)&g_xh[(size_t)m * DM + j] = hp;
    *(uint2*)&g_xl[(size_t)m * DM + j] = lp;
}

// fused: W_delta row k -> g_w1 cols [0,1024); W_B/W_C/pad -> cols [1024,1152)
__global__ void __launch_bounds__(256) convert_wdbc(
    const float* __restrict__ W, const float* __restrict__ WB, const float* __restrict__ WC)
{
    int k = blockIdx.x, t = threadIdx.x;
    int j = t * 4;
    float4 v = *(const float4*)&W[(size_t)k * DM + j];
    uint2 hp, lp; split4(v, hp, lp);
    *(uint2*)&g_w1[(size_t)k * NB1 + j]        = hp;
    *(uint2*)&g_w1[(size_t)(k + DM) * NB1 + j] = lp;
    if (t < 128) {
        float bv = 0.f;
        if (t < SD) bv = WB[k * SD + t];
        else if (t < 2 * SD) bv = WC[k * SD + t - SD];
        __nv_bfloat16 h = __float2bfloat16(bv);
        __nv_bfloat16 l = __float2bfloat16(bv - __bfloat162float(h));
        g_w1[(size_t)k * NB1 + DM + t]        = h;
        g_w1[(size_t)(k + DM) * NB1 + DM + t] = l;
    }
}

__global__ void __launch_bounds__(256) convert_wc(const float* __restrict__ W)
{
    int k = blockIdx.x, j = threadIdx.x * 4;
    float4 v = *(const float4*)&W[(size_t)k * DM + j];
    uint2 hp, lp; split4(v, hp, lp);
    *(uint2*)&g_w2[(size_t)k * DM + j]        = hp;
    *(uint2*)&g_w2[(size_t)(k + DM) * DM + j] = lp;
}

// ---------------- chunked selective scan ------------------------------------------
#define TC 128
__global__ void __launch_bounds__(256) scan_pass1(
    const float* __restrict__ x, const float* __restrict__ A_log)
{
    int blk  = blockIdx.x;
    int c    = blk & (NCH - 1);
    int dblk = (blk >> 4) & 63;
    int b    = blk >> 10;
    int tid  = threadIdx.x;
    int g    = tid >> 4, n = tid & 15;
    int d0   = dblk << 4, d = d0 + g;

    __shared__ float s_delta[TC][16];
    __shared__ float s_x    [TC][16];
    __shared__ float s_B    [TC][16];

    float a2 = -__expf(A_log[d * SD + n]) * LOG2E;
    float h = 0.f, sdt = 0.f;

    const float* dbase = g_delta + ((size_t)b * SEQ) * DM + d0;
    const float* xbase = x       + ((size_t)b * SEQ) * DM + d0;
    const float* Bbase = g_Bsel  + ((size_t)b * SEQ) * SD;
    int lr = tid >> 4, lc = tid & 15;
    int tstart = c * CHL;

    for (int t0 = tstart; t0 < tstart + CHL; t0 += TC) {
        __syncthreads();
        for (int r = lr; r < TC; r += 16) {
            s_delta[r][lc] = dbase[(size_t)(t0 + r) * DM + lc];
            s_x[r][lc]     = xbase[(size_t)(t0 + r) * DM + lc];
            s_B[r][lc]     = Bbase[(size_t)(t0 + r) * SD + lc];
        }
        __syncthreads();
#pragma unroll 8
        for (int t = 0; t < TC; t++) {
            float dt = s_delta[t][g];
            float xv = s_x[t][g];
            float bn = s_B[t][n];
            h = fmaf(h, exp2f(dt * a2), dt * xv * bn);
            sdt += dt;
        }
    }
    size_t ci = ((size_t)(b * NCH + c) * DM + d) * SD + n;
    g_hchunk[ci] = h;
    if (n == 0) g_sumdel[(size_t)(b * NCH + c) * DM + d] = sdt;
}

__global__ void __launch_bounds__(256) scan_pass2(const float* __restrict__ A_log)
{
    int idx = blockIdx.x * 256 + threadIdx.x;
    int n = idx & 15, d = (idx >> 4) & (DM - 1), b = idx >> 14;
    float a2 = -__expf(A_log[d * SD + n]) * LOG2E;
    float H = 0.f;
#pragma unroll
    for (int c = 0; c < NCH; c++) {
        size_t ci = ((size_t)(b * NCH + c) * DM + d) * SD + n;
        g_hinit[ci] = H;
        float S = g_sumdel[(size_t)(b * NCH + c) * DM + d];
        H = exp2f(a2 * S) * H + g_hchunk[ci];
    }
}

__global__ void __launch_bounds__(256) scan_pass3(
    const float* __restrict__ x, const float* __restrict__ A_log)
{
    int blk  = blockIdx.x;
    int c    = blk & (NCH - 1);
    int dblk = (blk >> 4) & 63;
    int b    = blk >> 10;
    int tid  = threadIdx.x;
    int g    = tid >> 4, n = tid & 15;
    int d0   = dblk << 4, d = d0 + g;

    __shared__ float s_delta[TC][16];
    __shared__ float s_x    [TC][16];
    __shared__ float s_B    [TC][16];
    __shared__ float s_C    [TC][16];
    __shared__ float s_y    [TC][16];

    float a2 = -__expf(A_log[d * SD + n]) * LOG2E;
    float h = g_hinit[((size_t)(b * NCH + c) * DM + d) * SD + n];

    const float* dbase = g_delta + ((size_t)b * SEQ) * DM + d0;
    const float* xbase = x       + ((size_t)b * SEQ) * DM + d0;
    const float* Bbase = g_Bsel  + ((size_t)b * SEQ) * SD;
    const float* Cbase = g_Csel  + ((size_t)b * SEQ) * SD;
    float*       ybase = g_ssm   + ((size_t)b * SEQ) * DM + d0;
    int lr = tid >> 4, lc = tid & 15;
    int tstart = c * CHL;

    for (int t0 = tstart; t0 < tstart + CHL; t0 += TC) {
        __syncthreads();
        for (int r = lr; r < TC; r += 16) {
            s_delta[r][lc] = dbase[(size_t)(t0 + r) * DM + lc];
            s_x[r][lc]     = xbase[(size_t)(t0 + r) * DM + lc];
            s_B[r][lc]     = Bbase[(size_t)(t0 + r) * SD + lc];
            s_C[r][lc]     = Cbase[(size_t)(t0 + r) * SD + lc];
        }
        __syncthreads();
#pragma unroll 4
        for (int t = 0; t < TC; t++) {
            float dt = s_delta[t][g];
            float xv = s_x[t][g];
            float bn = s_B[t][n];
            float cn = s_C[t][n];
            h = fmaf(h, exp2f(dt * a2), dt * xv * bn);
            float p = h * cn;
            p += __shfl_xor_sync(0xffffffffu, p, 8);
            p += __shfl_xor_sync(0xffffffffu, p, 4);
            p += __shfl_xor_sync(0xffffffffu, p, 2);
            p += __shfl_xor_sync(0xffffffffu, p, 1);
            if (n == 0) s_y[t][g] = p;
        }
        __syncthreads();
        for (int r = lr; r < TC; r += 16)
            ybase[(size_t)(t0 + r) * DM + lc] = s_y[r][lc];
    }
}

// ---------------- layernorm -> bf16 splits + h_final ------------------------------
__global__ void __launch_bounds__(256) ln_kernel(
    const float* __restrict__ gamma, const float* __restrict__ beta)
{
    int m = blockIdx.x;
    const float* row = g_ssm + (size_t)m * DM;
    int tid = threadIdx.x;
    float4 v = *(const float4*)&row[tid * 4];
    float s  = v.x + v.y + v.z + v.w;
    float ss = v.x*v.x + v.y*v.y + v.z*v.z + v.w*v.w;
#pragma unroll
    for (int o = 16; o > 0; o >>= 1) {
        s  += __shfl_xor_sync(0xffffffffu, s,  o);
        ss += __shfl_xor_sync(0xffffffffu, ss, o);
    }
    __shared__ float rs[8], rss[8];
    if ((tid & 31) == 0) { rs[tid >> 5] = s; rss[tid >> 5] = ss; }
    __syncthreads();
    s = 0.f; ss = 0.f;
#pragma unroll
    for (int i = 0; i < 8; i++) { s += rs[i]; ss += rss[i]; }
    float mu  = s * (1.0f / DM);
    float var = ss * (1.0f / DM) - mu * mu;
    float inv = rsqrtf(var + 1e-5f);
    float4 g4 = *(const float4*)&gamma[tid * 4];
    float4 b4 = *(const float4*)&beta[tid * 4];
    v.x = (v.x - mu) * inv * g4.x + b4.x;
    v.y = (v.y - mu) * inv * g4.y + b4.y;
    v.z = (v.z - mu) * inv * g4.z + b4.z;
    v.w = (v.w - mu) * inv * g4.w + b4.w;

    uint2 hp, lp; split4(v, hp, lp);
    *(uint2*)&g_sh[(size_t)m * DM + tid * 4] = hp;
    *(uint2*)&g_sl[(size_t)m * DM + tid * 4] = lp;

    if ((m & (SEQ - 1)) == SEQ - 1) {
        int b = m / SEQ;
        *(float4*)&g_hfinal[b * DM + tid * 4] = v;
    }
}

// ---------------- h_proj = h_final @ W_imp -----------------------------------------
__global__ void __launch_bounds__(256) hproj_kernel(const float* __restrict__ Wimp)
{
    int b = blockIdx.y;
    int j = blockIdx.x * 256 + threadIdx.x;
    __shared__ float hf[DM];
    for (int i = threadIdx.x; i < DM; i += 256) hf[i] = g_hfinal[b * DM + i];
    __syncthreads();
    float acc = 0.f;
#pragma unroll 8
    for (int d = 0; d < DM; d++)
        acc = fmaf(hf[d], Wimp[(size_t)d * DM + j], acc);
    g_hproj[b * DM + j] = acc;
}

// ---------------- raw_importance -----------------------------------------------------
__global__ void __launch_bounds__(256) raw_kernel(
    const float* __restrict__ x, float* __restrict__ out_raw)
{
    int m    = (blockIdx.x * 256 + threadIdx.x) >> 5;
    int lane = threadIdx.x & 31;
    int b    = m >> 12;
    const float* xr = x + (size_t)m * DM;
    const float* hp = g_hproj + b * DM;
    float acc = 0.f;
    for (int d = lane * 4; d < DM; d += 128) {
        float4 xv = *(const float4*)&xr[d];
        float4 hv = *(const float4*)&hp[d];
        acc += xv.x*hv.x + xv.y*hv.y + xv.z*hv.z + xv.w*hv.w;
    }
#pragma unroll
    for (int o = 16; o > 0; o >>= 1) acc += __shfl_xor_sync(0xffffffffu, acc, o);
    if (lane == 0) { g_raw[m] = acc; out_raw[m] = acc; }
}

// ---------------- softmax over seq ---------------------------------------------------
__global__ void __launch_bounds__(1024) softmax_kernel(float* __restrict__ out_imp)
{
    int b   = blockIdx.x;
    int tid = threadIdx.x;
    const float* r = g_raw + (size_t)b * SEQ;
    float4 rv = *(const float4*)&r[tid * 4];
    float v0 = rv.x * 2.0f, v1 = rv.y * 2.0f, v2 = rv.z * 2.0f, v3 = rv.w * 2.0f;
    float mx = fmaxf(fmaxf(v0, v1), fmaxf(v2, v3));

    __shared__ float swarp[32];
    __shared__ float bval;
#pragma unroll
    for (int o = 16; o > 0; o >>= 1) mx = fmaxf(mx, __shfl_xor_sync(0xffffffffu, mx, o));
    if ((tid & 31) == 0) swarp[tid >> 5] = mx;
    __syncthreads();
    if (tid < 32) {
        float v = swarp[tid];
#pragma unroll
        for (int o = 16; o > 0; o >>= 1) v = fmaxf(v, __shfl_xor_sync(0xffffffffu, v, o));
        if (tid == 0) bval = v;
    }
    __syncthreads();
    float gmax = bval;
    float e0 = __expf(v0 - gmax), e1 = __expf(v1 - gmax);
    float e2 = __expf(v2 - gmax), e3 = __expf(v3 - gmax);
    float sum = e0 + e1 + e2 + e3;
#pragma unroll
    for (int o = 16; o > 0; o >>= 1) sum += __shfl_xor_sync(0xffffffffu, sum, o);
    __syncthreads();
    if ((tid & 31) == 0) swarp[tid >> 5] = sum;
    __syncthreads();
    if (tid < 32) {
        float v = swarp[tid];
#pragma unroll
        for (int o = 16; o > 0; o >>= 1) v += __shfl_xor_sync(0xffffffffu, v, o);
        if (tid == 0) bval = v;
    }
    __syncthreads();
    float inv = 1.0f / bval;
    float4 o4; o4.x = e0 * inv; o4.y = e1 * inv; o4.z = e2 * inv; o4.w = e3 * inv;
    *(float4*)&out_imp[(size_t)b * SEQ + tid * 4] = o4;
}

// ---------------- launch ---------------------------------------------------------------
extern "C" void kernel_launch(void* const* d_in, const int* in_sizes, int n_in,
                              void* d_out, int out_size)
{
    const float* x       = (const float*)d_in[0];
    const float* A_log   = (const float*)d_in[1];
    const float* W_delta = (const float*)d_in[2];
    const float* W_B     = (const float*)d_in[3];
    const float* W_C     = (const float*)d_in[4];
    const float* gamma   = (const float*)d_in[5];
    const float* beta    = (const float*)d_in[6];
    const float* W_ctx   = (const float*)d_in[7];
    const float* scale   = (const float*)d_in[8];
    const float* W_imp   = (const float*)d_in[9];

    float* out     = (float*)d_out;
    float* out_imp = out;
    float* out_ctx = out + M_ROWS;
    float* out_raw = out + M_ROWS + (size_t)M_ROWS * DM;

    __nv_bfloat16 *p_xh, *p_xl, *p_sh, *p_sl, *p_w1, *p_w2;
    cudaGetSymbolAddress((void**)&p_xh, g_xh);
    cudaGetSymbolAddress((void**)&p_xl, g_xl);
    cudaGetSymbolAddress((void**)&p_sh, g_sh);
    cudaGetSymbolAddress((void**)&p_sl, g_sl);
    cudaGetSymbolAddress((void**)&p_w1, g_w1);
    cudaGetSymbolAddress((void**)&p_w2, g_w2);

    cudaFuncSetAttribute(hmma_gemm<0>, cudaFuncAttributeMaxDynamicSharedMemorySize, GSMEM);
    cudaFuncSetAttribute(hmma_gemm<1>, cudaFuncAttributeMaxDynamicSharedMemorySize, GSMEM);

    // launch order: ncu captures launch #4 -> gemm1
    convert_x   <<<M_ROWS, 256>>>(x);
    convert_wdbc<<<DM, 256>>>(W_delta, W_B, W_C);
    convert_wc  <<<DM, 256>>>(W_ctx);

    // (4) GEMM1: delta (softplus) + B_sel + C_sel
    hmma_gemm<1><<<dim3(NB1 / 128, M_ROWS / 128), 256, GSMEM>>>(
        p_xh, p_xl, p_w1, p_w1 + (size_t)DM * NB1, nullptr, nullptr, NB1);

    scan_pass1<<<BATCH * 64 * NCH, 256>>>(x, A_log);
    scan_pass2<<<128, 256>>>(A_log);
    scan_pass3<<<BATCH * 64 * NCH, 256>>>(x, A_log);

    ln_kernel<<<M_ROWS, 256>>>(gamma, beta);

    hproj_kernel<<<dim3(DM / 256, BATCH), 256>>>(W_imp);
    raw_kernel<<<M_ROWS / 8, 256>>>(x, out_raw);
    softmax_kernel<<<BATCH, 1024>>>(out_imp);

    // GEMM2: context = ln(ssm) @ W_ctx * scale
    hmma_gemm<0><<<dim3(DM / 128, M_ROWS / 128), 256, GSMEM>>>(
        p_sh, p_sl, p_w2, p_w2 + (size_t)DM * DM, out_ctx, scale, DM);
}